// round 1
// baseline (speedup 1.0000x reference)
#include <cuda_runtime.h>
#include <math.h>

#define BB 4
#define SS 2048
#define DD 1024
#define EE 8
#define K2 2048
#define EPSV 1e-6f
#define NCHUNK 16
#define CHUNK (SS / NCHUNK)   // 128

// ---------------- scratch (device globals; no allocation allowed) ----------------
__device__ float g_x[BB * SS * DD];       // normalized x
__device__ float g_xmean[BB * DD];
__device__ float g_probs[BB * EE];
__device__ float g_Whg[BB * K2 * DD];     // mixed hg weights
__device__ float g_Wout[BB * DD * DD];    // mixed out weights
__device__ float g_hg[(long)BB * SS * K2];
__device__ float g_c[BB * SS * DD];
__device__ float g_v[BB * SS * DD];
__device__ float g_h[BB * SS * DD];
__device__ float g_chunkC[BB * NCHUNK * DD];
__device__ float g_chunkH[BB * NCHUNK * DD];
__device__ float g_hin[BB * NCHUNK * DD];

// ---------------- 1. RMSNorm ----------------
__global__ void rmsnorm_kernel(const float* __restrict__ inp, const float* __restrict__ nw) {
    int row = blockIdx.x;                       // b*S + s
    const float* in = inp + (long)row * DD;
    float* out = g_x + (long)row * DD;
    float ss = 0.f;
    for (int d = threadIdx.x; d < DD; d += 256) { float t = in[d]; ss += t * t; }
    __shared__ float red[256];
    red[threadIdx.x] = ss; __syncthreads();
    for (int s = 128; s > 0; s >>= 1) {
        if (threadIdx.x < s) red[threadIdx.x] += red[threadIdx.x + s];
        __syncthreads();
    }
    float scale = rsqrtf(red[0] * (1.0f / DD) + EPSV);
    for (int d = threadIdx.x; d < DD; d += 256) out[d] = in[d] * scale * nw[d];
}

// ---------------- 2. column mean over S (deterministic) ----------------
__global__ void colmean_kernel() {
    int t = blockIdx.x * blockDim.x + threadIdx.x;
    if (t >= BB * DD) return;
    int b = t / DD, d = t % DD;
    float s = 0.f;
    const float* base = g_x + (long)b * SS * DD + d;
    for (int i = 0; i < SS; i++) s += base[(long)i * DD];
    g_xmean[t] = s * (1.0f / SS);
}

// ---------------- 3. router logits + softmax ----------------
__global__ void router_kernel(const float* __restrict__ rw, const float* __restrict__ rb) {
    __shared__ float logits[BB * EE];
    int tid = threadIdx.x, warp = tid / 32, lane = tid % 32;
    for (int p = warp; p < BB * EE; p += 8) {
        int b = p / EE, e = p % EE;
        float s = 0.f;
        for (int d = lane; d < DD; d += 32) s += g_xmean[b * DD + d] * rw[e * DD + d];
        for (int o = 16; o > 0; o >>= 1) s += __shfl_xor_sync(0xffffffffu, s, o);
        if (lane == 0) logits[p] = s + rb[e];
    }
    __syncthreads();
    if (tid < BB) {
        float mx = -1e30f;
        for (int e = 0; e < EE; e++) mx = fmaxf(mx, logits[tid * EE + e]);
        float ex[EE]; float sum = 0.f;
        for (int e = 0; e < EE; e++) { ex[e] = expf(logits[tid * EE + e] - mx); sum += ex[e]; }
        float inv = 1.0f / sum;
        for (int e = 0; e < EE; e++) g_probs[tid * EE + e] = ex[e] * inv;
    }
}

// ---------------- 4. mix expert weights ----------------
__global__ void mix_hg_kernel(const float* __restrict__ w) {
    __shared__ float p[BB * EE];
    if (threadIdx.x < BB * EE) p[threadIdx.x] = g_probs[threadIdx.x];
    __syncthreads();
    long idx = (long)blockIdx.x * blockDim.x + threadIdx.x;   // over K2*DD
    if (idx >= (long)K2 * DD) return;
    float a0 = 0, a1 = 0, a2 = 0, a3 = 0;
    #pragma unroll
    for (int e = 0; e < EE; e++) {
        float wv = w[(long)e * K2 * DD + idx];
        a0 = fmaf(p[0 * EE + e], wv, a0);
        a1 = fmaf(p[1 * EE + e], wv, a1);
        a2 = fmaf(p[2 * EE + e], wv, a2);
        a3 = fmaf(p[3 * EE + e], wv, a3);
    }
    g_Whg[0L * K2 * DD + idx] = a0;
    g_Whg[1L * K2 * DD + idx] = a1;
    g_Whg[2L * K2 * DD + idx] = a2;
    g_Whg[3L * K2 * DD + idx] = a3;
}

__global__ void mix_out_kernel(const float* __restrict__ w) {
    __shared__ float p[BB * EE];
    if (threadIdx.x < BB * EE) p[threadIdx.x] = g_probs[threadIdx.x];
    __syncthreads();
    long idx = (long)blockIdx.x * blockDim.x + threadIdx.x;   // over DD*DD
    if (idx >= (long)DD * DD) return;
    float a0 = 0, a1 = 0, a2 = 0, a3 = 0;
    #pragma unroll
    for (int e = 0; e < EE; e++) {
        float wv = w[(long)e * DD * DD + idx];
        a0 = fmaf(p[0 * EE + e], wv, a0);
        a1 = fmaf(p[1 * EE + e], wv, a1);
        a2 = fmaf(p[2 * EE + e], wv, a2);
        a3 = fmaf(p[3 * EE + e], wv, a3);
    }
    g_Wout[0L * DD * DD + idx] = a0;
    g_Wout[1L * DD * DD + idx] = a1;
    g_Wout[2L * DD * DD + idx] = a2;
    g_Wout[3L * DD * DD + idx] = a3;
}

// ---------------- tiled NT GEMM: C[m,n] = sum_k A[m,k]*B[n,k] (+Add) ----------------
// BM=BN=128, BK=16, 256 threads, 8x8 per thread.
__global__ __launch_bounds__(256)
void gemm_nt_kernel(const float* __restrict__ Aall, const float* __restrict__ Ball,
                    float* __restrict__ Call, const float* __restrict__ AddAll,
                    int N, long strideB) {
    const int K = DD;
    const float* A = Aall + (long)blockIdx.z * SS * K;
    const float* Bm = Ball + (long)blockIdx.z * strideB;
    float* C = Call + (long)blockIdx.z * SS * N;
    const float* Add = AddAll ? (AddAll + (long)blockIdx.z * SS * N) : nullptr;

    __shared__ float As[16][132];
    __shared__ float Bs[16][132];

    int tid = threadIdx.x;
    int row0 = blockIdx.y * 128;
    int col0 = blockIdx.x * 128;
    int la_r = tid >> 2;             // 0..63
    int la_c = (tid & 3) * 4;        // 0,4,8,12

    float acc[8][8];
    #pragma unroll
    for (int i = 0; i < 8; i++)
        #pragma unroll
        for (int j = 0; j < 8; j++) acc[i][j] = 0.f;

    int tm = (tid >> 4) * 8;
    int tn = (tid & 15) * 8;

    for (int k0 = 0; k0 < K; k0 += 16) {
        #pragma unroll
        for (int i = 0; i < 2; i++) {
            int r = la_r + i * 64;
            float4 va = *(const float4*)&A[(long)(row0 + r) * K + k0 + la_c];
            As[la_c + 0][r] = va.x; As[la_c + 1][r] = va.y;
            As[la_c + 2][r] = va.z; As[la_c + 3][r] = va.w;
            float4 vb = *(const float4*)&Bm[(long)(col0 + r) * K + k0 + la_c];
            Bs[la_c + 0][r] = vb.x; Bs[la_c + 1][r] = vb.y;
            Bs[la_c + 2][r] = vb.z; Bs[la_c + 3][r] = vb.w;
        }
        __syncthreads();
        #pragma unroll
        for (int kk = 0; kk < 16; kk++) {
            float a[8], b[8];
            *(float4*)&a[0] = *(const float4*)&As[kk][tm];
            *(float4*)&a[4] = *(const float4*)&As[kk][tm + 4];
            *(float4*)&b[0] = *(const float4*)&Bs[kk][tn];
            *(float4*)&b[4] = *(const float4*)&Bs[kk][tn + 4];
            #pragma unroll
            for (int i = 0; i < 8; i++)
                #pragma unroll
                for (int j = 0; j < 8; j++)
                    acc[i][j] = fmaf(a[i], b[j], acc[i][j]);
        }
        __syncthreads();
    }

    #pragma unroll
    for (int i = 0; i < 8; i++) {
        long rbase = (long)(row0 + tm + i) * N + col0 + tn;
        #pragma unroll
        for (int j4 = 0; j4 < 2; j4++) {
            float4 v;
            v.x = acc[i][j4 * 4 + 0]; v.y = acc[i][j4 * 4 + 1];
            v.z = acc[i][j4 * 4 + 2]; v.w = acc[i][j4 * 4 + 3];
            if (Add) {
                float4 ad = *(const float4*)&Add[rbase + j4 * 4];
                v.x += ad.x; v.y += ad.y; v.z += ad.z; v.w += ad.w;
            }
            *(float4*)&C[rbase + j4 * 4] = v;
        }
    }
}

// ---------------- 6. elementwise c, v ----------------
// c = sigmoid(-gate) ; v = sigmoid(gate) * (hidden>=0 ? hidden+0.5 : sigmoid(hidden))
__global__ void cv_kernel() {
    long idx = (long)blockIdx.x * blockDim.x + threadIdx.x;   // over B*S*D
    if (idx >= (long)BB * SS * DD) return;
    int j = (int)(idx % DD);
    long row = idx / DD;                                      // b*S+s
    long base = row * K2;
    float hidden = g_hg[base + j];
    float gate   = g_hg[base + DD + j];
    float t = expf(-fabsf(gate));
    float inv = 1.0f / (1.0f + t);
    float c, sp;
    if (gate >= 0.f) { sp = inv; c = t * inv; }
    else             { sp = t * inv; c = inv; }
    float gh = (hidden >= 0.f) ? (hidden + 0.5f) : (1.0f / (1.0f + expf(-hidden)));
    g_c[idx] = c;
    g_v[idx] = sp * gh;
}

// ---------------- 7-9. chunked scan: h_t = c_t*h_{t-1} + v_t ----------------
__global__ void scanA_kernel() {
    int t = blockIdx.x * blockDim.x + threadIdx.x;   // (b,ch,j)
    if (t >= BB * NCHUNK * DD) return;
    int j = t % DD, ch = (t / DD) % NCHUNK, b = t / (DD * NCHUNK);
    long base = ((long)b * SS + (long)ch * CHUNK) * DD + j;
    float h = 0.f, C = 1.f;
    #pragma unroll 4
    for (int i = 0; i < CHUNK; i++) {
        float c = g_c[base + (long)i * DD];
        float v = g_v[base + (long)i * DD];
        h = fmaf(c, h, v);
        C *= c;
    }
    g_chunkC[t] = C;
    g_chunkH[t] = h;
}

__global__ void scanB_kernel() {
    int t = blockIdx.x * blockDim.x + threadIdx.x;   // (b,j)
    if (t >= BB * DD) return;
    int b = t / DD, j = t % DD;
    float hin = 0.f;
    for (int ch = 0; ch < NCHUNK; ch++) {
        int u = (b * NCHUNK + ch) * DD + j;
        g_hin[u] = hin;
        hin = fmaf(g_chunkC[u], hin, g_chunkH[u]);
    }
}

__global__ void scanC_kernel() {
    int t = blockIdx.x * blockDim.x + threadIdx.x;
    if (t >= BB * NCHUNK * DD) return;
    int j = t % DD, ch = (t / DD) % NCHUNK, b = t / (DD * NCHUNK);
    long base = ((long)b * SS + (long)ch * CHUNK) * DD + j;
    float h = g_hin[t];
    #pragma unroll 4
    for (int i = 0; i < CHUNK; i++) {
        float c = g_c[base + (long)i * DD];
        float v = g_v[base + (long)i * DD];
        h = fmaf(c, h, v);
        g_h[base + (long)i * DD] = h;
    }
}

// ---------------- 11. tail: new_state + aux_loss ----------------
__global__ void tail_kernel(float* __restrict__ out) {
    int t = blockIdx.x * blockDim.x + threadIdx.x;
    if (t < BB * DD) {
        int b = t / DD, d = t % DD;
        out[(long)BB * SS * DD + t] = g_h[((long)b * SS + (SS - 1)) * DD + d];
    }
    if (t == 0) out[(long)BB * SS * DD + BB * DD] = 0.f;
}

// ---------------- launch ----------------
extern "C" void kernel_launch(void* const* d_in, const int* in_sizes, int n_in,
                              void* d_out, int out_size) {
    const float* inputs   = (const float*)d_in[0];
    const float* norm_w   = (const float*)d_in[1];
    const float* router_w = (const float*)d_in[2];
    const float* router_b = (const float*)d_in[3];
    const float* w_hg     = (const float*)d_in[4];
    const float* w_out    = (const float*)d_in[5];
    float* out = (float*)d_out;

    float* x_p;     cudaGetSymbolAddress((void**)&x_p, g_x);
    float* Whg_p;   cudaGetSymbolAddress((void**)&Whg_p, g_Whg);
    float* Wout_p;  cudaGetSymbolAddress((void**)&Wout_p, g_Wout);
    float* hg_p;    cudaGetSymbolAddress((void**)&hg_p, g_hg);
    float* h_p;     cudaGetSymbolAddress((void**)&h_p, g_h);

    rmsnorm_kernel<<<BB * SS, 256>>>(inputs, norm_w);
    colmean_kernel<<<(BB * DD + 255) / 256, 256>>>();
    router_kernel<<<1, 256>>>(router_w, router_b);
    mix_hg_kernel<<<(K2 * DD) / 256, 256>>>(w_hg);
    mix_out_kernel<<<(DD * DD) / 256, 256>>>(w_out);

    // hg = x @ Whg^T : M=S, N=K2, K=D, per-batch strides
    gemm_nt_kernel<<<dim3(K2 / 128, SS / 128, BB), 256>>>(
        x_p, Whg_p, hg_p, nullptr, K2, (long)K2 * DD);

    cv_kernel<<<(int)(((long)BB * SS * DD + 255) / 256), 256>>>();

    scanA_kernel<<<(BB * NCHUNK * DD + 255) / 256, 256>>>();
    scanB_kernel<<<(BB * DD + 255) / 256, 256>>>();
    scanC_kernel<<<(BB * NCHUNK * DD + 255) / 256, 256>>>();

    // out = h @ Wout^T + inputs : M=S, N=D, K=D, written straight into d_out
    gemm_nt_kernel<<<dim3(DD / 128, SS / 128, BB), 256>>>(
        h_p, Wout_p, out, inputs, DD, (long)DD * DD);

    tail_kernel<<<(BB * DD + 255) / 256, 256>>>(out);
}

// round 4
// speedup vs baseline: 2.0897x; 2.0897x over previous
#include <cuda_runtime.h>
#include <math.h>

#define BB 4
#define SS 2048
#define DD 1024
#define EE 8
#define K2 2048
#define EPSV 1e-6f
#define NCHUNK 16
#define CHUNK (SS / NCHUNK)   // 128

// ---------------- scratch (device globals; no allocation allowed) ----------------
__device__ float g_x[BB * SS * DD];       // normalized x
__device__ float g_xmean[BB * DD];
__device__ float g_probs[BB * EE];
__device__ float g_Whg[BB * K2 * DD];     // mixed hg weights
__device__ float g_Wout[BB * DD * DD];    // mixed out weights
__device__ float g_hg[(long)BB * SS * K2];
__device__ float g_c[BB * SS * DD];
__device__ float g_v[BB * SS * DD];
__device__ float g_h[BB * SS * DD];
__device__ float g_chunkC[BB * NCHUNK * DD];
__device__ float g_chunkH[BB * NCHUNK * DD];
__device__ float g_hin[BB * NCHUNK * DD];

// ---------------- 1. RMSNorm ----------------
__global__ void rmsnorm_kernel(const float* __restrict__ inp, const float* __restrict__ nw) {
    int row = blockIdx.x;                       // b*S + s
    const float* in = inp + (long)row * DD;
    float* out = g_x + (long)row * DD;
    float ss = 0.f;
    for (int d = threadIdx.x; d < DD; d += 256) { float t = in[d]; ss += t * t; }
    __shared__ float red[256];
    red[threadIdx.x] = ss; __syncthreads();
    for (int s = 128; s > 0; s >>= 1) {
        if (threadIdx.x < s) red[threadIdx.x] += red[threadIdx.x + s];
        __syncthreads();
    }
    float scale = rsqrtf(red[0] * (1.0f / DD) + EPSV);
    for (int d = threadIdx.x; d < DD; d += 256) out[d] = in[d] * scale * nw[d];
}

// ---------------- 2. column mean over S (deterministic) ----------------
__global__ void colmean_kernel() {
    int t = blockIdx.x * blockDim.x + threadIdx.x;
    if (t >= BB * DD) return;
    int b = t / DD, d = t % DD;
    float s = 0.f;
    const float* base = g_x + (long)b * SS * DD + d;
    for (int i = 0; i < SS; i++) s += base[(long)i * DD];
    g_xmean[t] = s * (1.0f / SS);
}

// ---------------- 3. router logits + softmax ----------------
__global__ void router_kernel(const float* __restrict__ rw, const float* __restrict__ rb) {
    __shared__ float logits[BB * EE];
    int tid = threadIdx.x, warp = tid / 32, lane = tid % 32;
    for (int p = warp; p < BB * EE; p += 8) {
        int b = p / EE, e = p % EE;
        float s = 0.f;
        for (int d = lane; d < DD; d += 32) s += g_xmean[b * DD + d] * rw[e * DD + d];
        for (int o = 16; o > 0; o >>= 1) s += __shfl_xor_sync(0xffffffffu, s, o);
        if (lane == 0) logits[p] = s + rb[e];
    }
    __syncthreads();
    if (tid < BB) {
        float mx = -1e30f;
        for (int e = 0; e < EE; e++) mx = fmaxf(mx, logits[tid * EE + e]);
        float ex[EE]; float sum = 0.f;
        for (int e = 0; e < EE; e++) { ex[e] = expf(logits[tid * EE + e] - mx); sum += ex[e]; }
        float inv = 1.0f / sum;
        for (int e = 0; e < EE; e++) g_probs[tid * EE + e] = ex[e] * inv;
    }
}

// ---------------- 4. mix expert weights ----------------
__global__ void mix_hg_kernel(const float* __restrict__ w) {
    __shared__ float p[BB * EE];
    if (threadIdx.x < BB * EE) p[threadIdx.x] = g_probs[threadIdx.x];
    __syncthreads();
    long idx = (long)blockIdx.x * blockDim.x + threadIdx.x;   // over K2*DD
    if (idx >= (long)K2 * DD) return;
    float a0 = 0, a1 = 0, a2 = 0, a3 = 0;
    #pragma unroll
    for (int e = 0; e < EE; e++) {
        float wv = w[(long)e * K2 * DD + idx];
        a0 = fmaf(p[0 * EE + e], wv, a0);
        a1 = fmaf(p[1 * EE + e], wv, a1);
        a2 = fmaf(p[2 * EE + e], wv, a2);
        a3 = fmaf(p[3 * EE + e], wv, a3);
    }
    g_Whg[0L * K2 * DD + idx] = a0;
    g_Whg[1L * K2 * DD + idx] = a1;
    g_Whg[2L * K2 * DD + idx] = a2;
    g_Whg[3L * K2 * DD + idx] = a3;
}

__global__ void mix_out_kernel(const float* __restrict__ w) {
    __shared__ float p[BB * EE];
    if (threadIdx.x < BB * EE) p[threadIdx.x] = g_probs[threadIdx.x];
    __syncthreads();
    long idx = (long)blockIdx.x * blockDim.x + threadIdx.x;   // over DD*DD
    if (idx >= (long)DD * DD) return;
    float a0 = 0, a1 = 0, a2 = 0, a3 = 0;
    #pragma unroll
    for (int e = 0; e < EE; e++) {
        float wv = w[(long)e * DD * DD + idx];
        a0 = fmaf(p[0 * EE + e], wv, a0);
        a1 = fmaf(p[1 * EE + e], wv, a1);
        a2 = fmaf(p[2 * EE + e], wv, a2);
        a3 = fmaf(p[3 * EE + e], wv, a3);
    }
    g_Wout[0L * DD * DD + idx] = a0;
    g_Wout[1L * DD * DD + idx] = a1;
    g_Wout[2L * DD * DD + idx] = a2;
    g_Wout[3L * DD * DD + idx] = a3;
}

// ---------------- TF32 tensor-core NT GEMM ----------------
// C[m,n] = sum_k A[m,k]*B[n,k] (+Add). BM=BN=128, BK=16, 256 threads.
// Warp grid 2(M) x 4(N): each warp owns 64x32, tiled as 4x4 m16n8k8 mma.

__device__ __forceinline__ unsigned f2tf32(float x) {
    unsigned r;
    asm("cvt.rna.tf32.f32 %0, %1;" : "=r"(r) : "f"(x));
    return r;
}

#define BKT 16
#define SPAD 20   // smem row stride in words (16 + 4): conflict-free frag LDS

__global__ __launch_bounds__(256)
void gemm_tf32_kernel(const float* __restrict__ Aall, const float* __restrict__ Ball,
                      float* __restrict__ Call, const float* __restrict__ AddAll,
                      int N, long strideB) {
    const int K = DD;
    const float* A = Aall + (long)blockIdx.z * SS * K;
    const float* Bm = Ball + (long)blockIdx.z * strideB;
    float* C = Call + (long)blockIdx.z * SS * N;
    const float* Add = AddAll ? (AddAll + (long)blockIdx.z * SS * N) : nullptr;

    __shared__ __align__(16) unsigned As[2][128][SPAD];
    __shared__ __align__(16) unsigned Bs[2][128][SPAD];

    int tid = threadIdx.x;
    int lane = tid & 31;
    int w = tid >> 5;
    int wm = w & 1;          // 0..1 -> M offset wm*64
    int wn = w >> 1;         // 0..3 -> N offset wn*32
    int g = lane >> 2;       // group id 0..7
    int tg = lane & 3;       // thread-in-group 0..3

    int row0 = blockIdx.y * 128;
    int col0 = blockIdx.x * 128;

    // global-load mapping: each thread loads 2 float4 from A and 2 from B
    int lrow = tid >> 2;            // 0..63
    int lcol = (tid & 3) * 4;       // 0,4,8,12

    float acc[4][4][4];
    #pragma unroll
    for (int i = 0; i < 4; i++)
        #pragma unroll
        for (int j = 0; j < 4; j++)
            #pragma unroll
            for (int r = 0; r < 4; r++) acc[i][j][r] = 0.f;

    const int NTILES = K / BKT;     // 64

    float4 av0, av1, bv0, bv1;

    // prefetch tile 0
    av0 = *(const float4*)&A[(long)(row0 + lrow) * K + lcol];
    av1 = *(const float4*)&A[(long)(row0 + lrow + 64) * K + lcol];
    bv0 = *(const float4*)&Bm[(long)(col0 + lrow) * K + lcol];
    bv1 = *(const float4*)&Bm[(long)(col0 + lrow + 64) * K + lcol];
    *(uint4*)&As[0][lrow][lcol]      = make_uint4(f2tf32(av0.x), f2tf32(av0.y), f2tf32(av0.z), f2tf32(av0.w));
    *(uint4*)&As[0][lrow + 64][lcol] = make_uint4(f2tf32(av1.x), f2tf32(av1.y), f2tf32(av1.z), f2tf32(av1.w));
    *(uint4*)&Bs[0][lrow][lcol]      = make_uint4(f2tf32(bv0.x), f2tf32(bv0.y), f2tf32(bv0.z), f2tf32(bv0.w));
    *(uint4*)&Bs[0][lrow + 64][lcol] = make_uint4(f2tf32(bv1.x), f2tf32(bv1.y), f2tf32(bv1.z), f2tf32(bv1.w));
    __syncthreads();

    for (int kt = 0; kt < NTILES; kt++) {
        int buf = kt & 1;
        if (kt + 1 < NTILES) {
            int k0 = (kt + 1) * BKT;
            av0 = *(const float4*)&A[(long)(row0 + lrow) * K + k0 + lcol];
            av1 = *(const float4*)&A[(long)(row0 + lrow + 64) * K + k0 + lcol];
            bv0 = *(const float4*)&Bm[(long)(col0 + lrow) * K + k0 + lcol];
            bv1 = *(const float4*)&Bm[(long)(col0 + lrow + 64) * K + k0 + lcol];
        }

        #pragma unroll
        for (int ks = 0; ks < BKT; ks += 8) {
            unsigned af[4][4], bf[4][2];
            #pragma unroll
            for (int mt = 0; mt < 4; mt++) {
                int r = wm * 64 + mt * 16 + g;
                af[mt][0] = As[buf][r][ks + tg];
                af[mt][1] = As[buf][r + 8][ks + tg];
                af[mt][2] = As[buf][r][ks + tg + 4];
                af[mt][3] = As[buf][r + 8][ks + tg + 4];
            }
            #pragma unroll
            for (int nt = 0; nt < 4; nt++) {
                int c = wn * 32 + nt * 8 + g;
                bf[nt][0] = Bs[buf][c][ks + tg];
                bf[nt][1] = Bs[buf][c][ks + tg + 4];
            }
            #pragma unroll
            for (int mt = 0; mt < 4; mt++)
                #pragma unroll
                for (int nt = 0; nt < 4; nt++) {
                    asm volatile(
                        "mma.sync.aligned.m16n8k8.row.col.f32.tf32.tf32.f32 "
                        "{%0,%1,%2,%3}, {%4,%5,%6,%7}, {%8,%9}, {%0,%1,%2,%3};\n"
                        : "+f"(acc[mt][nt][0]), "+f"(acc[mt][nt][1]),
                          "+f"(acc[mt][nt][2]), "+f"(acc[mt][nt][3])
                        : "r"(af[mt][0]), "r"(af[mt][1]), "r"(af[mt][2]), "r"(af[mt][3]),
                          "r"(bf[nt][0]), "r"(bf[nt][1]));
                }
        }

        if (kt + 1 < NTILES) {
            int nb = buf ^ 1;
            *(uint4*)&As[nb][lrow][lcol]      = make_uint4(f2tf32(av0.x), f2tf32(av0.y), f2tf32(av0.z), f2tf32(av0.w));
            *(uint4*)&As[nb][lrow + 64][lcol] = make_uint4(f2tf32(av1.x), f2tf32(av1.y), f2tf32(av1.z), f2tf32(av1.w));
            *(uint4*)&Bs[nb][lrow][lcol]      = make_uint4(f2tf32(bv0.x), f2tf32(bv0.y), f2tf32(bv0.z), f2tf32(bv0.w));
            *(uint4*)&Bs[nb][lrow + 64][lcol] = make_uint4(f2tf32(bv1.x), f2tf32(bv1.y), f2tf32(bv1.z), f2tf32(bv1.w));
        }
        __syncthreads();
    }

    // epilogue
    #pragma unroll
    for (int mt = 0; mt < 4; mt++) {
        int row = row0 + wm * 64 + mt * 16 + g;
        #pragma unroll
        for (int nt = 0; nt < 4; nt++) {
            int col = col0 + wn * 32 + nt * 8 + 2 * tg;
            float2 v0 = make_float2(acc[mt][nt][0], acc[mt][nt][1]);
            float2 v1 = make_float2(acc[mt][nt][2], acc[mt][nt][3]);
            if (Add) {
                float2 a0 = *(const float2*)&Add[(long)row * N + col];
                float2 a1 = *(const float2*)&Add[(long)(row + 8) * N + col];
                v0.x += a0.x; v0.y += a0.y; v1.x += a1.x; v1.y += a1.y;
            }
            *(float2*)&C[(long)row * N + col] = v0;
            *(float2*)&C[(long)(row + 8) * N + col] = v1;
        }
    }
}

// ---------------- 6. elementwise c, v ----------------
// c = sigmoid(-gate) ; v = sigmoid(gate) * (hidden>=0 ? hidden+0.5 : sigmoid(hidden))
__global__ void cv_kernel() {
    long idx = (long)blockIdx.x * blockDim.x + threadIdx.x;   // over B*S*D
    if (idx >= (long)BB * SS * DD) return;
    int j = (int)(idx % DD);
    long row = idx / DD;                                      // b*S+s
    long base = row * K2;
    float hidden = g_hg[base + j];
    float gate   = g_hg[base + DD + j];
    float t = expf(-fabsf(gate));
    float inv = 1.0f / (1.0f + t);
    float c, sp;
    if (gate >= 0.f) { sp = inv; c = t * inv; }
    else             { sp = t * inv; c = inv; }
    float gh = (hidden >= 0.f) ? (hidden + 0.5f) : (1.0f / (1.0f + expf(-hidden)));
    g_c[idx] = c;
    g_v[idx] = sp * gh;
}

// ---------------- 7-9. chunked scan: h_t = c_t*h_{t-1} + v_t ----------------
__global__ void scanA_kernel() {
    int t = blockIdx.x * blockDim.x + threadIdx.x;   // (b,ch,j)
    if (t >= BB * NCHUNK * DD) return;
    int j = t % DD, ch = (t / DD) % NCHUNK, b = t / (DD * NCHUNK);
    long base = ((long)b * SS + (long)ch * CHUNK) * DD + j;
    float h = 0.f, C = 1.f;
    #pragma unroll 4
    for (int i = 0; i < CHUNK; i++) {
        float c = g_c[base + (long)i * DD];
        float v = g_v[base + (long)i * DD];
        h = fmaf(c, h, v);
        C *= c;
    }
    g_chunkC[t] = C;
    g_chunkH[t] = h;
}

__global__ void scanB_kernel() {
    int t = blockIdx.x * blockDim.x + threadIdx.x;   // (b,j)
    if (t >= BB * DD) return;
    int b = t / DD, j = t % DD;
    float hin = 0.f;
    for (int ch = 0; ch < NCHUNK; ch++) {
        int u = (b * NCHUNK + ch) * DD + j;
        g_hin[u] = hin;
        hin = fmaf(g_chunkC[u], hin, g_chunkH[u]);
    }
}

__global__ void scanC_kernel() {
    int t = blockIdx.x * blockDim.x + threadIdx.x;
    if (t >= BB * NCHUNK * DD) return;
    int j = t % DD, ch = (t / DD) % NCHUNK, b = t / (DD * NCHUNK);
    long base = ((long)b * SS + (long)ch * CHUNK) * DD + j;
    float h = g_hin[t];
    #pragma unroll 4
    for (int i = 0; i < CHUNK; i++) {
        float c = g_c[base + (long)i * DD];
        float v = g_v[base + (long)i * DD];
        h = fmaf(c, h, v);
        g_h[base + (long)i * DD] = h;
    }
}

// ---------------- 11. tail: new_state + aux_loss ----------------
__global__ void tail_kernel(float* __restrict__ out) {
    int t = blockIdx.x * blockDim.x + threadIdx.x;
    if (t < BB * DD) {
        int b = t / DD, d = t % DD;
        out[(long)BB * SS * DD + t] = g_h[((long)b * SS + (SS - 1)) * DD + d];
    }
    if (t == 0) out[(long)BB * SS * DD + BB * DD] = 0.f;
}

// ---------------- launch ----------------
extern "C" void kernel_launch(void* const* d_in, const int* in_sizes, int n_in,
                              void* d_out, int out_size) {
    const float* inputs   = (const float*)d_in[0];
    const float* norm_w   = (const float*)d_in[1];
    const float* router_w = (const float*)d_in[2];
    const float* router_b = (const float*)d_in[3];
    const float* w_hg     = (const float*)d_in[4];
    const float* w_out    = (const float*)d_in[5];
    float* out = (float*)d_out;

    float* x_p;     cudaGetSymbolAddress((void**)&x_p, g_x);
    float* Whg_p;   cudaGetSymbolAddress((void**)&Whg_p, g_Whg);
    float* Wout_p;  cudaGetSymbolAddress((void**)&Wout_p, g_Wout);
    float* hg_p;    cudaGetSymbolAddress((void**)&hg_p, g_hg);
    float* h_p;     cudaGetSymbolAddress((void**)&h_p, g_h);

    rmsnorm_kernel<<<BB * SS, 256>>>(inputs, norm_w);
    colmean_kernel<<<(BB * DD + 255) / 256, 256>>>();
    router_kernel<<<1, 256>>>(router_w, router_b);
    mix_hg_kernel<<<(K2 * DD) / 256, 256>>>(w_hg);
    mix_out_kernel<<<(DD * DD) / 256, 256>>>(w_out);

    // hg = x @ Whg^T : M=S, N=K2, K=D, per-batch strides
    gemm_tf32_kernel<<<dim3(K2 / 128, SS / 128, BB), 256>>>(
        x_p, Whg_p, hg_p, nullptr, K2, (long)K2 * DD);

    cv_kernel<<<(int)(((long)BB * SS * DD + 255) / 256), 256>>>();

    scanA_kernel<<<(BB * NCHUNK * DD + 255) / 256, 256>>>();
    scanB_kernel<<<(BB * DD + 255) / 256, 256>>>();
    scanC_kernel<<<(BB * NCHUNK * DD + 255) / 256, 256>>>();

    // out = h @ Wout^T + inputs : M=S, N=D, K=D, written straight into d_out
    gemm_tf32_kernel<<<dim3(DD / 128, SS / 128, BB), 256>>>(
        h_p, Wout_p, out, inputs, DD, (long)DD * DD);

    tail_kernel<<<(BB * DD + 255) / 256, 256>>>(out);
}

// round 8
// speedup vs baseline: 2.1931x; 1.0495x over previous
#include <cuda_runtime.h>
#include <math.h>
#include <stdint.h>

#define BB 4
#define SS 2048
#define DD 1024
#define EE 8
#define K2 2048
#define EPSV 1e-6f
#define NCHUNK 16
#define CHUNK (SS / NCHUNK)   // 128

// ---------------- GEMM tiling ----------------
#define BM 128
#define BN 256
#define BK 32
#define NKC (DD / BK)            // 32
#define SPAD 36                  // smem row stride in words (32 + 4)
#define A_STAGE_WORDS (BM * SPAD)            // 4608
#define B_STAGE_WORDS (BN * SPAD)            // 9216
#define STAGE_WORDS   (A_STAGE_WORDS + B_STAGE_WORDS)   // 13824
#define STAGE_BYTES   (STAGE_WORDS * 4)                 // 55296
#define NSTAGE 3
#define GEMM_SMEM (NSTAGE * STAGE_BYTES)                // 165888

// ---------------- scratch ----------------
__device__ float g_x[BB * SS * DD];
__device__ float g_xmean[BB * DD];
__device__ float g_probs[BB * EE];
__device__ float g_Whg[BB * K2 * DD];
__device__ float g_Wout[BB * DD * DD];
__device__ float g_hg[(long)BB * SS * K2];
__device__ float g_h[BB * SS * DD];
__device__ float g_chunkC[BB * NCHUNK * DD];
__device__ float g_chunkH[BB * NCHUNK * DD];
__device__ float g_hin[BB * NCHUNK * DD];

// ---------------- helpers ----------------
__device__ __forceinline__ unsigned f2tf32(float x) {
    unsigned r;
    asm("cvt.rna.tf32.f32 %0, %1;" : "=r"(r) : "f"(x));
    return r;
}
__device__ __forceinline__ float tf32r(float x) { return __uint_as_float(f2tf32(x)); }

__device__ __forceinline__ uint32_t smem_u32(const void* p) {
    uint32_t a;
    asm("{ .reg .u64 t; cvta.to.shared.u64 t, %1; cvt.u32.u64 %0, t; }" : "=r"(a) : "l"(p));
    return a;
}
__device__ __forceinline__ void cpasync16(uint32_t dst, const void* src) {
    asm volatile("cp.async.cg.shared.global [%0], [%1], 16;" :: "r"(dst), "l"(src));
}

// ---------------- 1. RMSNorm (writes TF32-rounded x) ----------------
__global__ void rmsnorm_kernel(const float* __restrict__ inp, const float* __restrict__ nw) {
    int row = blockIdx.x;
    const float* in = inp + (long)row * DD;
    float* out = g_x + (long)row * DD;
    float ss = 0.f;
    for (int d = threadIdx.x; d < DD; d += 256) { float t = in[d]; ss += t * t; }
    __shared__ float red[256];
    red[threadIdx.x] = ss; __syncthreads();
    for (int s = 128; s > 0; s >>= 1) {
        if (threadIdx.x < s) red[threadIdx.x] += red[threadIdx.x + s];
        __syncthreads();
    }
    float scale = rsqrtf(red[0] * (1.0f / DD) + EPSV);
    for (int d = threadIdx.x; d < DD; d += 256) out[d] = tf32r(in[d] * scale * nw[d]);
}

// ---------------- 2. column mean ----------------
__global__ void colmean_kernel() {
    int t = blockIdx.x * blockDim.x + threadIdx.x;
    if (t >= BB * DD) return;
    int b = t / DD, d = t % DD;
    float s = 0.f;
    const float* base = g_x + (long)b * SS * DD + d;
    for (int i = 0; i < SS; i++) s += base[(long)i * DD];
    g_xmean[t] = s * (1.0f / SS);
}

// ---------------- 3. router ----------------
__global__ void router_kernel(const float* __restrict__ rw, const float* __restrict__ rb) {
    __shared__ float logits[BB * EE];
    int tid = threadIdx.x, warp = tid / 32, lane = tid % 32;
    for (int p = warp; p < BB * EE; p += 8) {
        int b = p / EE, e = p % EE;
        float s = 0.f;
        for (int d = lane; d < DD; d += 32) s += g_xmean[b * DD + d] * rw[e * DD + d];
        for (int o = 16; o > 0; o >>= 1) s += __shfl_xor_sync(0xffffffffu, s, o);
        if (lane == 0) logits[p] = s + rb[e];
    }
    __syncthreads();
    if (tid < BB) {
        float mx = -1e30f;
        for (int e = 0; e < EE; e++) mx = fmaxf(mx, logits[tid * EE + e]);
        float ex[EE]; float sum = 0.f;
        for (int e = 0; e < EE; e++) { ex[e] = expf(logits[tid * EE + e] - mx); sum += ex[e]; }
        float inv = 1.0f / sum;
        for (int e = 0; e < EE; e++) g_probs[tid * EE + e] = ex[e] * inv;
    }
}

// ---------------- 4. mix expert weights (float4, TF32-rounded outputs) ----------------
__global__ void mix_hg_kernel(const float* __restrict__ w) {
    __shared__ float p[BB * EE];
    if (threadIdx.x < BB * EE) p[threadIdx.x] = g_probs[threadIdx.x];
    __syncthreads();
    long idx = ((long)blockIdx.x * blockDim.x + threadIdx.x) * 4;   // over K2*DD
    if (idx >= (long)K2 * DD) return;
    float4 a0 = {0,0,0,0}, a1 = {0,0,0,0}, a2 = {0,0,0,0}, a3 = {0,0,0,0};
    #pragma unroll
    for (int e = 0; e < EE; e++) {
        float4 wv = *(const float4*)&w[(long)e * K2 * DD + idx];
        float p0 = p[0*EE+e], p1 = p[1*EE+e], p2 = p[2*EE+e], p3 = p[3*EE+e];
        a0.x = fmaf(p0, wv.x, a0.x); a0.y = fmaf(p0, wv.y, a0.y); a0.z = fmaf(p0, wv.z, a0.z); a0.w = fmaf(p0, wv.w, a0.w);
        a1.x = fmaf(p1, wv.x, a1.x); a1.y = fmaf(p1, wv.y, a1.y); a1.z = fmaf(p1, wv.z, a1.z); a1.w = fmaf(p1, wv.w, a1.w);
        a2.x = fmaf(p2, wv.x, a2.x); a2.y = fmaf(p2, wv.y, a2.y); a2.z = fmaf(p2, wv.z, a2.z); a2.w = fmaf(p2, wv.w, a2.w);
        a3.x = fmaf(p3, wv.x, a3.x); a3.y = fmaf(p3, wv.y, a3.y); a3.z = fmaf(p3, wv.z, a3.z); a3.w = fmaf(p3, wv.w, a3.w);
    }
    #define RND4(v) make_float4(tf32r(v.x), tf32r(v.y), tf32r(v.z), tf32r(v.w))
    *(float4*)&g_Whg[0L * K2 * DD + idx] = RND4(a0);
    *(float4*)&g_Whg[1L * K2 * DD + idx] = RND4(a1);
    *(float4*)&g_Whg[2L * K2 * DD + idx] = RND4(a2);
    *(float4*)&g_Whg[3L * K2 * DD + idx] = RND4(a3);
}

__global__ void mix_out_kernel(const float* __restrict__ w) {
    __shared__ float p[BB * EE];
    if (threadIdx.x < BB * EE) p[threadIdx.x] = g_probs[threadIdx.x];
    __syncthreads();
    long idx = ((long)blockIdx.x * blockDim.x + threadIdx.x) * 4;   // over DD*DD
    if (idx >= (long)DD * DD) return;
    float4 a0 = {0,0,0,0}, a1 = {0,0,0,0}, a2 = {0,0,0,0}, a3 = {0,0,0,0};
    #pragma unroll
    for (int e = 0; e < EE; e++) {
        float4 wv = *(const float4*)&w[(long)e * DD * DD + idx];
        float p0 = p[0*EE+e], p1 = p[1*EE+e], p2 = p[2*EE+e], p3 = p[3*EE+e];
        a0.x = fmaf(p0, wv.x, a0.x); a0.y = fmaf(p0, wv.y, a0.y); a0.z = fmaf(p0, wv.z, a0.z); a0.w = fmaf(p0, wv.w, a0.w);
        a1.x = fmaf(p1, wv.x, a1.x); a1.y = fmaf(p1, wv.y, a1.y); a1.z = fmaf(p1, wv.z, a1.z); a1.w = fmaf(p1, wv.w, a1.w);
        a2.x = fmaf(p2, wv.x, a2.x); a2.y = fmaf(p2, wv.y, a2.y); a2.z = fmaf(p2, wv.z, a2.z); a2.w = fmaf(p2, wv.w, a2.w);
        a3.x = fmaf(p3, wv.x, a3.x); a3.y = fmaf(p3, wv.y, a3.y); a3.z = fmaf(p3, wv.z, a3.z); a3.w = fmaf(p3, wv.w, a3.w);
    }
    *(float4*)&g_Wout[0L * DD * DD + idx] = RND4(a0);
    *(float4*)&g_Wout[1L * DD * DD + idx] = RND4(a1);
    *(float4*)&g_Wout[2L * DD * DD + idx] = RND4(a2);
    *(float4*)&g_Wout[3L * DD * DD + idx] = RND4(a3);
}

// ---------------- TF32 mma.sync NT GEMM: C = A @ B^T (+Add) ----------------
// Tile 128x256, 256 threads (8 warps as 2M x 4N, warp tile 64x64).
// Inputs pre-rounded to TF32 -> cp.async direct to smem, no cvt in loop.
__global__ __launch_bounds__(256, 1)
void gemm_tf32_kernel(const float* __restrict__ Aall, const float* __restrict__ Ball,
                      float* __restrict__ Call, const float* __restrict__ AddAll,
                      int N, long strideB) {
    extern __shared__ __align__(16) float smf[];
    const uint32_t sb = smem_u32(smf);
    const int K = DD;
    const float* A  = Aall + (long)blockIdx.z * SS * K;
    const float* Bm = Ball + (long)blockIdx.z * strideB;
    float* C = Call + (long)blockIdx.z * SS * N;
    const float* Add = AddAll ? (AddAll + (long)blockIdx.z * SS * N) : nullptr;

    const int tid = threadIdx.x;
    const int lane = tid & 31;
    const int w = tid >> 5;
    const int wm = w & 1;            // M offset wm*64
    const int wn = w >> 1;           // N offset wn*64
    const int g = lane >> 2;         // 0..7
    const int tg = lane & 3;         // 0..3

    const int row0 = blockIdx.y * BM;
    const int col0 = blockIdx.x * BN;

    float acc[4][8][4];
    #pragma unroll
    for (int i = 0; i < 4; i++)
        #pragma unroll
        for (int j = 0; j < 8; j++)
            #pragma unroll
            for (int r = 0; r < 4; r++) acc[i][j][r] = 0.f;

    // fill one stage: A 128x32 (1024 float4), B 256x32 (2048 float4)
    auto fill = [&](int stage, int kc) {
        uint32_t abase = sb + stage * STAGE_BYTES;
        uint32_t bbase = abase + A_STAGE_WORDS * 4;
        const float* Ak = A + kc * BK;
        #pragma unroll
        for (int i = 0; i < 4; i++) {
            int q = tid + i * 256, r = q >> 3, cg = q & 7;
            cpasync16(abase + r * (SPAD * 4) + cg * 16, Ak + (long)(row0 + r) * K + cg * 4);
        }
        const float* Bk = Bm + kc * BK;
        #pragma unroll
        for (int i = 0; i < 8; i++) {
            int q = tid + i * 256, r = q >> 3, cg = q & 7;
            cpasync16(bbase + r * (SPAD * 4) + cg * 16, Bk + (long)(col0 + r) * K + cg * 4);
        }
        asm volatile("cp.async.commit_group;" ::: "memory");
    };

    fill(0, 0);
    fill(1, 1);

    for (int kt = 0; kt < NKC; kt++) {
        if (kt + 2 < NKC) asm volatile("cp.async.wait_group 1;" ::: "memory");
        else              asm volatile("cp.async.wait_group 0;" ::: "memory");
        __syncthreads();

        if (kt + 2 < NKC) fill((kt + 2) % NSTAGE, kt + 2);

        const float* sA = smf + (kt % NSTAGE) * STAGE_WORDS;
        const float* sB = sA + A_STAGE_WORDS;

        #pragma unroll
        for (int ks = 0; ks < BK; ks += 8) {
            unsigned af[4][4], bf[8][2];
            #pragma unroll
            for (int mt = 0; mt < 4; mt++) {
                int r = wm * 64 + mt * 16 + g;
                af[mt][0] = __float_as_uint(sA[r * SPAD + ks + tg]);
                af[mt][1] = __float_as_uint(sA[(r + 8) * SPAD + ks + tg]);
                af[mt][2] = __float_as_uint(sA[r * SPAD + ks + tg + 4]);
                af[mt][3] = __float_as_uint(sA[(r + 8) * SPAD + ks + tg + 4]);
            }
            #pragma unroll
            for (int nt = 0; nt < 8; nt++) {
                int c = wn * 64 + nt * 8 + g;
                bf[nt][0] = __float_as_uint(sB[c * SPAD + ks + tg]);
                bf[nt][1] = __float_as_uint(sB[c * SPAD + ks + tg + 4]);
            }
            #pragma unroll
            for (int mt = 0; mt < 4; mt++)
                #pragma unroll
                for (int nt = 0; nt < 8; nt++) {
                    asm volatile(
                        "mma.sync.aligned.m16n8k8.row.col.f32.tf32.tf32.f32 "
                        "{%0,%1,%2,%3}, {%4,%5,%6,%7}, {%8,%9}, {%0,%1,%2,%3};\n"
                        : "+f"(acc[mt][nt][0]), "+f"(acc[mt][nt][1]),
                          "+f"(acc[mt][nt][2]), "+f"(acc[mt][nt][3])
                        : "r"(af[mt][0]), "r"(af[mt][1]), "r"(af[mt][2]), "r"(af[mt][3]),
                          "r"(bf[nt][0]), "r"(bf[nt][1]));
                }
        }
        __syncthreads();
    }

    // epilogue
    #pragma unroll
    for (int mt = 0; mt < 4; mt++) {
        int row = row0 + wm * 64 + mt * 16 + g;
        #pragma unroll
        for (int nt = 0; nt < 8; nt++) {
            int col = col0 + wn * 64 + nt * 8 + 2 * tg;
            float2 v0 = make_float2(acc[mt][nt][0], acc[mt][nt][1]);
            float2 v1 = make_float2(acc[mt][nt][2], acc[mt][nt][3]);
            if (Add) {
                float2 a0 = *(const float2*)&Add[(long)row * N + col];
                float2 a1 = *(const float2*)&Add[(long)(row + 8) * N + col];
                v0.x += a0.x; v0.y += a0.y; v1.x += a1.x; v1.y += a1.y;
            }
            *(float2*)&C[(long)row * N + col] = v0;
            *(float2*)&C[(long)(row + 8) * N + col] = v1;
        }
    }
}

// ---------------- fused c,v from hg ----------------
__device__ __forceinline__ void cv_from_hg(float hidden, float gate, float& c, float& v) {
    float t = expf(-fabsf(gate));
    float inv = 1.0f / (1.0f + t);
    float sp;
    if (gate >= 0.f) { sp = inv; c = t * inv; }
    else             { sp = t * inv; c = inv; }
    float gh = (hidden >= 0.f) ? (hidden + 0.5f) : (1.0f / (1.0f + expf(-hidden)));
    v = sp * gh;
}

// ---------------- chunked scan: h_t = c_t*h_{t-1} + v_t ----------------
__global__ void scanA_kernel() {
    int t = blockIdx.x * blockDim.x + threadIdx.x;
    if (t >= BB * NCHUNK * DD) return;
    int j = t % DD, ch = (t / DD) % NCHUNK, b = t / (DD * NCHUNK);
    long rowbase = (long)b * SS + (long)ch * CHUNK;
    float h = 0.f, Cp = 1.f;
    for (int i = 0; i < CHUNK; i++) {
        long ro = (rowbase + i) * K2;
        float c, v;
        cv_from_hg(g_hg[ro + j], g_hg[ro + DD + j], c, v);
        h = fmaf(c, h, v);
        Cp *= c;
    }
    g_chunkC[t] = Cp;
    g_chunkH[t] = h;
}

__global__ void scanB_kernel() {
    int t = blockIdx.x * blockDim.x + threadIdx.x;
    if (t >= BB * DD) return;
    int b = t / DD, j = t % DD;
    float hin = 0.f;
    for (int ch = 0; ch < NCHUNK; ch++) {
        int u = (b * NCHUNK + ch) * DD + j;
        g_hin[u] = hin;
        hin = fmaf(g_chunkC[u], hin, g_chunkH[u]);
    }
}

__global__ void scanC_kernel(float* __restrict__ out) {
    int t = blockIdx.x * blockDim.x + threadIdx.x;
    if (t >= BB * NCHUNK * DD) return;
    int j = t % DD, ch = (t / DD) % NCHUNK, b = t / (DD * NCHUNK);
    long rowbase = (long)b * SS + (long)ch * CHUNK;
    float h = g_hin[t];
    for (int i = 0; i < CHUNK; i++) {
        long ro = (rowbase + i) * K2;
        float c, v;
        cv_from_hg(g_hg[ro + j], g_hg[ro + DD + j], c, v);
        h = fmaf(c, h, v);
        g_h[(rowbase + i) * DD + j] = tf32r(h);   // TF32-rounded for GEMM2
    }
    if (ch == NCHUNK - 1) out[(long)BB * SS * DD + b * DD + j] = h;  // new_state
    if (t == 0) out[(long)BB * SS * DD + BB * DD] = 0.f;             // aux_loss
}

// ---------------- launch ----------------
extern "C" void kernel_launch(void* const* d_in, const int* in_sizes, int n_in,
                              void* d_out, int out_size) {
    const float* inputs   = (const float*)d_in[0];
    const float* norm_w   = (const float*)d_in[1];
    const float* router_w = (const float*)d_in[2];
    const float* router_b = (const float*)d_in[3];
    const float* w_hg     = (const float*)d_in[4];
    const float* w_out    = (const float*)d_in[5];
    float* out = (float*)d_out;

    float* x_p;     cudaGetSymbolAddress((void**)&x_p, g_x);
    float* Whg_p;   cudaGetSymbolAddress((void**)&Whg_p, g_Whg);
    float* Wout_p;  cudaGetSymbolAddress((void**)&Wout_p, g_Wout);
    float* hg_p;    cudaGetSymbolAddress((void**)&hg_p, g_hg);
    float* h_p;     cudaGetSymbolAddress((void**)&h_p, g_h);

    cudaFuncSetAttribute(gemm_tf32_kernel,
                         cudaFuncAttributeMaxDynamicSharedMemorySize, GEMM_SMEM);

    rmsnorm_kernel<<<BB * SS, 256>>>(inputs, norm_w);
    colmean_kernel<<<(BB * DD + 255) / 256, 256>>>();
    router_kernel<<<1, 256>>>(router_w, router_b);
    mix_hg_kernel<<<(K2 * DD / 4) / 256, 256>>>(w_hg);
    mix_out_kernel<<<(DD * DD / 4) / 256, 256>>>(w_out);

    // hg = x @ Whg^T : M=S, N=K2, K=D
    gemm_tf32_kernel<<<dim3(K2 / BN, SS / BM, BB), 256, GEMM_SMEM>>>(
        x_p, Whg_p, hg_p, nullptr, K2, (long)K2 * DD);

    scanA_kernel<<<(BB * NCHUNK * DD + 255) / 256, 256>>>();
    scanB_kernel<<<(BB * DD + 255) / 256, 256>>>();
    scanC_kernel<<<(BB * NCHUNK * DD + 255) / 256, 256>>>(out);

    // out = h @ Wout^T + inputs
    gemm_tf32_kernel<<<dim3(DD / BN, SS / BM, BB), 256, GEMM_SMEM>>>(
        h_p, Wout_p, out, inputs, DD, (long)DD * DD);
}

// round 11
// speedup vs baseline: 3.1186x; 1.4220x over previous
#include <cuda_runtime.h>
#include <cuda_fp16.h>
#include <math.h>
#include <stdint.h>

#define BB 4
#define SS 2048
#define DD 1024
#define EE 8
#define K2 2048
#define EPSV 1e-6f
#define NCHUNK 16
#define CHUNK (SS / NCHUNK)   // 128

// ---------------- GEMM tiling (fp16 operands) ----------------
#define BM 128
#define BN 256
#define BK 64                     // halves per K-chunk (128 bytes/row)
#define NKC (DD / BK)             // 16
#define SPADH 72                  // smem row stride in halves (64 + 8)
#define A_STAGE_HALVES (BM * SPADH)              // 9216
#define B_STAGE_HALVES (BN * SPADH)              // 18432
#define STAGE_HALVES   (A_STAGE_HALVES + B_STAGE_HALVES)
#define STAGE_BYTES    (STAGE_HALVES * 2)        // 55296
#define NSTAGE 3
#define GEMM_SMEM (NSTAGE * STAGE_BYTES)         // 165888

// ---------------- scratch ----------------
__device__ __half g_x[BB * SS * DD];
__device__ float  g_xmean[BB * DD];
__device__ float  g_probs[BB * EE];
__device__ __half g_Whg[BB * K2 * DD];
__device__ __half g_Wout[BB * DD * DD];
__device__ float  g_hg[(long)BB * SS * K2];
__device__ __half g_h[BB * SS * DD];
__device__ float  g_chunkC[BB * NCHUNK * DD];
__device__ float  g_chunkH[BB * NCHUNK * DD];
__device__ float  g_hin[BB * NCHUNK * DD];

// ---------------- helpers ----------------
__device__ __forceinline__ uint32_t smem_u32(const void* p) {
    uint32_t a;
    asm("{ .reg .u64 t; cvta.to.shared.u64 t, %1; cvt.u32.u64 %0, t; }" : "=r"(a) : "l"(p));
    return a;
}
__device__ __forceinline__ void cpasync16(uint32_t dst, const void* src) {
    asm volatile("cp.async.cg.shared.global [%0], [%1], 16;" :: "r"(dst), "l"(src));
}

// ---------------- 1. RMSNorm (writes fp16 x) ----------------
__global__ void rmsnorm_kernel(const float* __restrict__ inp, const float* __restrict__ nw) {
    int row = blockIdx.x;
    const float* in = inp + (long)row * DD;
    __half* out = g_x + (long)row * DD;
    float ss = 0.f;
    for (int d = threadIdx.x; d < DD; d += 256) { float t = in[d]; ss += t * t; }
    __shared__ float red[256];
    red[threadIdx.x] = ss; __syncthreads();
    for (int s = 128; s > 0; s >>= 1) {
        if (threadIdx.x < s) red[threadIdx.x] += red[threadIdx.x + s];
        __syncthreads();
    }
    float scale = rsqrtf(red[0] * (1.0f / DD) + EPSV);
    for (int d = threadIdx.x; d < DD; d += 256) out[d] = __float2half_rn(in[d] * scale * nw[d]);
}

// ---------------- 2. column mean ----------------
__global__ void colmean_kernel() {
    int t = blockIdx.x * blockDim.x + threadIdx.x;
    if (t >= BB * DD) return;
    int b = t / DD, d = t % DD;
    float s = 0.f;
    const __half* base = g_x + (long)b * SS * DD + d;
    for (int i = 0; i < SS; i++) s += __half2float(base[(long)i * DD]);
    g_xmean[t] = s * (1.0f / SS);
}

// ---------------- 3. router ----------------
__global__ void router_kernel(const float* __restrict__ rw, const float* __restrict__ rb) {
    __shared__ float logits[BB * EE];
    int tid = threadIdx.x, warp = tid / 32, lane = tid % 32;
    for (int p = warp; p < BB * EE; p += 8) {
        int b = p / EE, e = p % EE;
        float s = 0.f;
        for (int d = lane; d < DD; d += 32) s += g_xmean[b * DD + d] * rw[e * DD + d];
        for (int o = 16; o > 0; o >>= 1) s += __shfl_xor_sync(0xffffffffu, s, o);
        if (lane == 0) logits[p] = s + rb[e];
    }
    __syncthreads();
    if (tid < BB) {
        float mx = -1e30f;
        for (int e = 0; e < EE; e++) mx = fmaxf(mx, logits[tid * EE + e]);
        float ex[EE]; float sum = 0.f;
        for (int e = 0; e < EE; e++) { ex[e] = expf(logits[tid * EE + e] - mx); sum += ex[e]; }
        float inv = 1.0f / sum;
        for (int e = 0; e < EE; e++) g_probs[tid * EE + e] = ex[e] * inv;
    }
}

// ---------------- 4. mix expert weights (fp32 accum, fp16 out) ----------------
__global__ void mix_hg_kernel(const float* __restrict__ w) {
    __shared__ float p[BB * EE];
    if (threadIdx.x < BB * EE) p[threadIdx.x] = g_probs[threadIdx.x];
    __syncthreads();
    long idx = ((long)blockIdx.x * blockDim.x + threadIdx.x) * 4;
    if (idx >= (long)K2 * DD) return;
    float4 a0 = {0,0,0,0}, a1 = {0,0,0,0}, a2 = {0,0,0,0}, a3 = {0,0,0,0};
    #pragma unroll
    for (int e = 0; e < EE; e++) {
        float4 wv = *(const float4*)&w[(long)e * K2 * DD + idx];
        float p0 = p[0*EE+e], p1 = p[1*EE+e], p2 = p[2*EE+e], p3 = p[3*EE+e];
        a0.x = fmaf(p0, wv.x, a0.x); a0.y = fmaf(p0, wv.y, a0.y); a0.z = fmaf(p0, wv.z, a0.z); a0.w = fmaf(p0, wv.w, a0.w);
        a1.x = fmaf(p1, wv.x, a1.x); a1.y = fmaf(p1, wv.y, a1.y); a1.z = fmaf(p1, wv.z, a1.z); a1.w = fmaf(p1, wv.w, a1.w);
        a2.x = fmaf(p2, wv.x, a2.x); a2.y = fmaf(p2, wv.y, a2.y); a2.z = fmaf(p2, wv.z, a2.z); a2.w = fmaf(p2, wv.w, a2.w);
        a3.x = fmaf(p3, wv.x, a3.x); a3.y = fmaf(p3, wv.y, a3.y); a3.z = fmaf(p3, wv.z, a3.z); a3.w = fmaf(p3, wv.w, a3.w);
    }
    #define STH4(dst, v) do { \
        *(__half2*)&(dst)[0] = __floats2half2_rn(v.x, v.y); \
        *(__half2*)&(dst)[2] = __floats2half2_rn(v.z, v.w); } while (0)
    STH4(&g_Whg[0L * K2 * DD + idx], a0);
    STH4(&g_Whg[1L * K2 * DD + idx], a1);
    STH4(&g_Whg[2L * K2 * DD + idx], a2);
    STH4(&g_Whg[3L * K2 * DD + idx], a3);
}

__global__ void mix_out_kernel(const float* __restrict__ w) {
    __shared__ float p[BB * EE];
    if (threadIdx.x < BB * EE) p[threadIdx.x] = g_probs[threadIdx.x];
    __syncthreads();
    long idx = ((long)blockIdx.x * blockDim.x + threadIdx.x) * 4;
    if (idx >= (long)DD * DD) return;
    float4 a0 = {0,0,0,0}, a1 = {0,0,0,0}, a2 = {0,0,0,0}, a3 = {0,0,0,0};
    #pragma unroll
    for (int e = 0; e < EE; e++) {
        float4 wv = *(const float4*)&w[(long)e * DD * DD + idx];
        float p0 = p[0*EE+e], p1 = p[1*EE+e], p2 = p[2*EE+e], p3 = p[3*EE+e];
        a0.x = fmaf(p0, wv.x, a0.x); a0.y = fmaf(p0, wv.y, a0.y); a0.z = fmaf(p0, wv.z, a0.z); a0.w = fmaf(p0, wv.w, a0.w);
        a1.x = fmaf(p1, wv.x, a1.x); a1.y = fmaf(p1, wv.y, a1.y); a1.z = fmaf(p1, wv.z, a1.z); a1.w = fmaf(p1, wv.w, a1.w);
        a2.x = fmaf(p2, wv.x, a2.x); a2.y = fmaf(p2, wv.y, a2.y); a2.z = fmaf(p2, wv.z, a2.z); a2.w = fmaf(p2, wv.w, a2.w);
        a3.x = fmaf(p3, wv.x, a3.x); a3.y = fmaf(p3, wv.y, a3.y); a3.z = fmaf(p3, wv.z, a3.z); a3.w = fmaf(p3, wv.w, a3.w);
    }
    STH4(&g_Wout[0L * DD * DD + idx], a0);
    STH4(&g_Wout[1L * DD * DD + idx], a1);
    STH4(&g_Wout[2L * DD * DD + idx], a2);
    STH4(&g_Wout[3L * DD * DD + idx], a3);
}

// ---------------- fp16 mma.sync NT GEMM: C = A @ B^T (+Add), fp32 accum ----------------
// Tile 128x256, 256 threads (8 warps 2M x 4N, warp tile 64x64), BK=64, 3-stage.
__global__ __launch_bounds__(256, 1)
void gemm_fp16_kernel(const __half* __restrict__ Aall, const __half* __restrict__ Ball,
                      float* __restrict__ Call, const float* __restrict__ AddAll,
                      int N, long strideB) {
    extern __shared__ __align__(16) __half smh[];
    const uint32_t sb = smem_u32(smh);
    const int K = DD;
    const __half* A  = Aall + (long)blockIdx.z * SS * K;
    const __half* Bm = Ball + (long)blockIdx.z * strideB;
    float* C = Call + (long)blockIdx.z * SS * N;
    const float* Add = AddAll ? (AddAll + (long)blockIdx.z * SS * N) : nullptr;

    const int tid = threadIdx.x;
    const int lane = tid & 31;
    const int w = tid >> 5;
    const int wm = w & 1;            // M offset wm*64
    const int wn = w >> 1;           // N offset wn*64
    const int g = lane >> 2;         // 0..7
    const int tg = lane & 3;         // 0..3

    const int row0 = blockIdx.y * BM;
    const int col0 = blockIdx.x * BN;

    float acc[4][8][4];
    #pragma unroll
    for (int i = 0; i < 4; i++)
        #pragma unroll
        for (int j = 0; j < 8; j++)
            #pragma unroll
            for (int r = 0; r < 4; r++) acc[i][j][r] = 0.f;

    // fill one stage: A 128x64 halves (1024 x 16B), B 256x64 (2048 x 16B)
    auto fill = [&](int stage, int kc) {
        uint32_t abase = sb + stage * STAGE_BYTES;
        uint32_t bbase = abase + A_STAGE_HALVES * 2;
        const __half* Ak = A + kc * BK;
        #pragma unroll
        for (int i = 0; i < 4; i++) {
            int q = tid + i * 256, r = q >> 3, cg = q & 7;
            cpasync16(abase + r * (SPADH * 2) + cg * 16, Ak + (long)(row0 + r) * K + cg * 8);
        }
        const __half* Bk = Bm + kc * BK;
        #pragma unroll
        for (int i = 0; i < 8; i++) {
            int q = tid + i * 256, r = q >> 3, cg = q & 7;
            cpasync16(bbase + r * (SPADH * 2) + cg * 16, Bk + (long)(col0 + r) * K + cg * 8);
        }
        asm volatile("cp.async.commit_group;" ::: "memory");
    };

    fill(0, 0);
    fill(1, 1);

    for (int kt = 0; kt < NKC; kt++) {
        if (kt + 2 < NKC) asm volatile("cp.async.wait_group 1;" ::: "memory");
        else              asm volatile("cp.async.wait_group 0;" ::: "memory");
        __syncthreads();

        if (kt + 2 < NKC) fill((kt + 2) % NSTAGE, kt + 2);

        const __half* sA = smh + (kt % NSTAGE) * STAGE_HALVES;
        const __half* sB = sA + A_STAGE_HALVES;

        #pragma unroll
        for (int ks = 0; ks < BK; ks += 16) {
            unsigned af[4][4], bf[8][2];
            #pragma unroll
            for (int mt = 0; mt < 4; mt++) {
                int r = wm * 64 + mt * 16 + g;
                af[mt][0] = *(const unsigned*)&sA[r * SPADH + ks + 2 * tg];
                af[mt][1] = *(const unsigned*)&sA[(r + 8) * SPADH + ks + 2 * tg];
                af[mt][2] = *(const unsigned*)&sA[r * SPADH + ks + 2 * tg + 8];
                af[mt][3] = *(const unsigned*)&sA[(r + 8) * SPADH + ks + 2 * tg + 8];
            }
            #pragma unroll
            for (int nt = 0; nt < 8; nt++) {
                int c = wn * 64 + nt * 8 + g;
                bf[nt][0] = *(const unsigned*)&sB[c * SPADH + ks + 2 * tg];
                bf[nt][1] = *(const unsigned*)&sB[c * SPADH + ks + 2 * tg + 8];
            }
            #pragma unroll
            for (int mt = 0; mt < 4; mt++)
                #pragma unroll
                for (int nt = 0; nt < 8; nt++) {
                    asm volatile(
                        "mma.sync.aligned.m16n8k16.row.col.f32.f16.f16.f32 "
                        "{%0,%1,%2,%3}, {%4,%5,%6,%7}, {%8,%9}, {%0,%1,%2,%3};\n"
                        : "+f"(acc[mt][nt][0]), "+f"(acc[mt][nt][1]),
                          "+f"(acc[mt][nt][2]), "+f"(acc[mt][nt][3])
                        : "r"(af[mt][0]), "r"(af[mt][1]), "r"(af[mt][2]), "r"(af[mt][3]),
                          "r"(bf[nt][0]), "r"(bf[nt][1]));
                }
        }
        __syncthreads();
    }

    // epilogue
    #pragma unroll
    for (int mt = 0; mt < 4; mt++) {
        int row = row0 + wm * 64 + mt * 16 + g;
        #pragma unroll
        for (int nt = 0; nt < 8; nt++) {
            int col = col0 + wn * 64 + nt * 8 + 2 * tg;
            float2 v0 = make_float2(acc[mt][nt][0], acc[mt][nt][1]);
            float2 v1 = make_float2(acc[mt][nt][2], acc[mt][nt][3]);
            if (Add) {
                float2 a0 = *(const float2*)&Add[(long)row * N + col];
                float2 a1 = *(const float2*)&Add[(long)(row + 8) * N + col];
                v0.x += a0.x; v0.y += a0.y; v1.x += a1.x; v1.y += a1.y;
            }
            *(float2*)&C[(long)row * N + col] = v0;
            *(float2*)&C[(long)(row + 8) * N + col] = v1;
        }
    }
}

// ---------------- fused c,v from hg ----------------
__device__ __forceinline__ void cv_from_hg(float hidden, float gate, float& c, float& v) {
    float t = expf(-fabsf(gate));
    float inv = 1.0f / (1.0f + t);
    float sp;
    if (gate >= 0.f) { sp = inv; c = t * inv; }
    else             { sp = t * inv; c = inv; }
    float gh = (hidden >= 0.f) ? (hidden + 0.5f) : (1.0f / (1.0f + expf(-hidden)));
    v = sp * gh;
}

// ---------------- chunked scan: h_t = c_t*h_{t-1} + v_t ----------------
__global__ void scanA_kernel() {
    int t = blockIdx.x * blockDim.x + threadIdx.x;
    if (t >= BB * NCHUNK * DD) return;
    int j = t % DD, ch = (t / DD) % NCHUNK, b = t / (DD * NCHUNK);
    long rowbase = (long)b * SS + (long)ch * CHUNK;
    float h = 0.f, Cp = 1.f;
    for (int i = 0; i < CHUNK; i++) {
        long ro = (rowbase + i) * K2;
        float c, v;
        cv_from_hg(g_hg[ro + j], g_hg[ro + DD + j], c, v);
        h = fmaf(c, h, v);
        Cp *= c;
    }
    g_chunkC[t] = Cp;
    g_chunkH[t] = h;
}

__global__ void scanB_kernel() {
    int t = blockIdx.x * blockDim.x + threadIdx.x;
    if (t >= BB * DD) return;
    int b = t / DD, j = t % DD;
    float hin = 0.f;
    for (int ch = 0; ch < NCHUNK; ch++) {
        int u = (b * NCHUNK + ch) * DD + j;
        g_hin[u] = hin;
        hin = fmaf(g_chunkC[u], hin, g_chunkH[u]);
    }
}

__global__ void scanC_kernel(float* __restrict__ out) {
    int t = blockIdx.x * blockDim.x + threadIdx.x;
    if (t >= BB * NCHUNK * DD) return;
    int j = t % DD, ch = (t / DD) % NCHUNK, b = t / (DD * NCHUNK);
    long rowbase = (long)b * SS + (long)ch * CHUNK;
    float h = g_hin[t];
    for (int i = 0; i < CHUNK; i++) {
        long ro = (rowbase + i) * K2;
        float c, v;
        cv_from_hg(g_hg[ro + j], g_hg[ro + DD + j], c, v);
        h = fmaf(c, h, v);
        g_h[(rowbase + i) * DD + j] = __float2half_rn(h);   // fp16 for GEMM2
    }
    if (ch == NCHUNK - 1) out[(long)BB * SS * DD + b * DD + j] = h;  // new_state (fp32)
    if (t == 0) out[(long)BB * SS * DD + BB * DD] = 0.f;             // aux_loss
}

// ---------------- launch ----------------
extern "C" void kernel_launch(void* const* d_in, const int* in_sizes, int n_in,
                              void* d_out, int out_size) {
    const float* inputs   = (const float*)d_in[0];
    const float* norm_w   = (const float*)d_in[1];
    const float* router_w = (const float*)d_in[2];
    const float* router_b = (const float*)d_in[3];
    const float* w_hg     = (const float*)d_in[4];
    const float* w_out    = (const float*)d_in[5];
    float* out = (float*)d_out;

    __half* x_p;    cudaGetSymbolAddress((void**)&x_p, g_x);
    __half* Whg_p;  cudaGetSymbolAddress((void**)&Whg_p, g_Whg);
    __half* Wout_p; cudaGetSymbolAddress((void**)&Wout_p, g_Wout);
    float* hg_p;    cudaGetSymbolAddress((void**)&hg_p, g_hg);
    __half* h_p;    cudaGetSymbolAddress((void**)&h_p, g_h);

    cudaFuncSetAttribute(gemm_fp16_kernel,
                         cudaFuncAttributeMaxDynamicSharedMemorySize, GEMM_SMEM);

    rmsnorm_kernel<<<BB * SS, 256>>>(inputs, norm_w);
    colmean_kernel<<<(BB * DD + 255) / 256, 256>>>();
    router_kernel<<<1, 256>>>(router_w, router_b);
    mix_hg_kernel<<<(K2 * DD / 4) / 256, 256>>>(w_hg);
    mix_out_kernel<<<(DD * DD / 4) / 256, 256>>>(w_out);

    // hg = x @ Whg^T : M=S, N=K2, K=D
    gemm_fp16_kernel<<<dim3(K2 / BN, SS / BM, BB), 256, GEMM_SMEM>>>(
        x_p, Whg_p, hg_p, nullptr, K2, (long)K2 * DD);

    scanA_kernel<<<(BB * NCHUNK * DD + 255) / 256, 256>>>();
    scanB_kernel<<<(BB * DD + 255) / 256, 256>>>();
    scanC_kernel<<<(BB * NCHUNK * DD + 255) / 256, 256>>>(out);

    // out = h @ Wout^T + inputs
    gemm_fp16_kernel<<<dim3(DD / BN, SS / BM, BB), 256, GEMM_SMEM>>>(
        h_p, Wout_p, out, inputs, DD, (long)DD * DD);
}

// round 12
// speedup vs baseline: 3.4006x; 1.0904x over previous
#include <cuda_runtime.h>
#include <cuda_fp16.h>
#include <math.h>
#include <stdint.h>

#define BB 4
#define SS 2048
#define DD 1024
#define EE 8
#define K2 2048
#define EPSV 1e-6f
#define NCHUNK 16
#define CHUNK (SS / NCHUNK)   // 128

// ---------------- GEMM tiling (fp16 operands) ----------------
#define BM 128
#define BK 64                     // halves per K-chunk (128 bytes/row)
#define NKC (DD / BK)             // 16
#define SPADH 72                  // smem row stride in halves (64 + 8)
#define A_STAGE_HALVES (BM * SPADH)              // 9216
#define NSTAGE 3

// ---------------- scratch ----------------
__device__ __half g_x[BB * SS * DD];
__device__ float  g_xmean[BB * DD];
__device__ float  g_probs[BB * EE];
__device__ __half g_Whg[BB * K2 * DD];    // row-permuted: 2j=hidden_j, 2j+1=gate_j
__device__ __half g_Wout[BB * DD * DD];
__device__ float  g_c[BB * SS * DD];
__device__ float  g_v[BB * SS * DD];
__device__ __half g_h[BB * SS * DD];
__device__ float  g_chunkC[BB * NCHUNK * DD];
__device__ float  g_chunkH[BB * NCHUNK * DD];
__device__ float  g_hin[BB * NCHUNK * DD];

// ---------------- helpers ----------------
__device__ __forceinline__ uint32_t smem_u32(const void* p) {
    uint32_t a;
    asm("{ .reg .u64 t; cvta.to.shared.u64 t, %1; cvt.u32.u64 %0, t; }" : "=r"(a) : "l"(p));
    return a;
}
__device__ __forceinline__ void cpasync16(uint32_t dst, const void* src) {
    asm volatile("cp.async.cg.shared.global [%0], [%1], 16;" :: "r"(dst), "l"(src));
}
// c = sigmoid(-gate); v = sigmoid(gate) * (hidden>=0 ? hidden+0.5 : sigmoid(hidden))
__device__ __forceinline__ void cv_from_hg(float hidden, float gate, float& c, float& v) {
    float t = expf(-fabsf(gate));
    float inv = 1.0f / (1.0f + t);
    float sp;
    if (gate >= 0.f) { sp = inv; c = t * inv; }
    else             { sp = t * inv; c = inv; }
    float gh = (hidden >= 0.f) ? (hidden + 0.5f) : (1.0f / (1.0f + expf(-hidden)));
    v = sp * gh;
}

// ---------------- 1. RMSNorm (writes fp16 x) ----------------
__global__ void rmsnorm_kernel(const float* __restrict__ inp, const float* __restrict__ nw) {
    int row = blockIdx.x;
    const float* in = inp + (long)row * DD;
    __half* out = g_x + (long)row * DD;
    float ss = 0.f;
    for (int d = threadIdx.x; d < DD; d += 256) { float t = in[d]; ss += t * t; }
    __shared__ float red[256];
    red[threadIdx.x] = ss; __syncthreads();
    for (int s = 128; s > 0; s >>= 1) {
        if (threadIdx.x < s) red[threadIdx.x] += red[threadIdx.x + s];
        __syncthreads();
    }
    float scale = rsqrtf(red[0] * (1.0f / DD) + EPSV);
    for (int d = threadIdx.x; d < DD; d += 256) out[d] = __float2half_rn(in[d] * scale * nw[d]);
}

// ---------------- 2. column mean ----------------
__global__ void colmean_kernel() {
    int t = blockIdx.x * blockDim.x + threadIdx.x;
    if (t >= BB * DD) return;
    int b = t / DD, d = t % DD;
    float s = 0.f;
    const __half* base = g_x + (long)b * SS * DD + d;
    for (int i = 0; i < SS; i++) s += __half2float(base[(long)i * DD]);
    g_xmean[t] = s * (1.0f / SS);
}

// ---------------- 3. router ----------------
__global__ void router_kernel(const float* __restrict__ rw, const float* __restrict__ rb) {
    __shared__ float logits[BB * EE];
    int tid = threadIdx.x, warp = tid / 32, lane = tid % 32;
    for (int p = warp; p < BB * EE; p += 8) {
        int b = p / EE, e = p % EE;
        float s = 0.f;
        for (int d = lane; d < DD; d += 32) s += g_xmean[b * DD + d] * rw[e * DD + d];
        for (int o = 16; o > 0; o >>= 1) s += __shfl_xor_sync(0xffffffffu, s, o);
        if (lane == 0) logits[p] = s + rb[e];
    }
    __syncthreads();
    if (tid < BB) {
        float mx = -1e30f;
        for (int e = 0; e < EE; e++) mx = fmaxf(mx, logits[tid * EE + e]);
        float ex[EE]; float sum = 0.f;
        for (int e = 0; e < EE; e++) { ex[e] = expf(logits[tid * EE + e] - mx); sum += ex[e]; }
        float inv = 1.0f / sum;
        for (int e = 0; e < EE; e++) g_probs[tid * EE + e] = ex[e] * inv;
    }
}

// ---------------- 4. mix expert weights (fp32 accum, fp16 out) ----------------
// hg weights written ROW-PERMUTED: output row 2j <- hidden_j (k=j),
// row 2j+1 <- gate_j (k=j+DD). GEMM1 then produces interleaved hidden/gate cols.
__global__ void mix_hg_kernel(const float* __restrict__ w) {
    __shared__ float p[BB * EE];
    if (threadIdx.x < BB * EE) p[threadIdx.x] = g_probs[threadIdx.x];
    __syncthreads();
    long idx = ((long)blockIdx.x * blockDim.x + threadIdx.x) * 4;
    if (idx >= (long)K2 * DD) return;
    int k = (int)(idx / DD), d = (int)(idx % DD);
    int pr = (k < DD) ? 2 * k : 2 * (k - DD) + 1;
    long pidx = (long)pr * DD + d;
    float4 a0 = {0,0,0,0}, a1 = {0,0,0,0}, a2 = {0,0,0,0}, a3 = {0,0,0,0};
    #pragma unroll
    for (int e = 0; e < EE; e++) {
        float4 wv = *(const float4*)&w[(long)e * K2 * DD + idx];
        float p0 = p[0*EE+e], p1 = p[1*EE+e], p2 = p[2*EE+e], p3 = p[3*EE+e];
        a0.x = fmaf(p0, wv.x, a0.x); a0.y = fmaf(p0, wv.y, a0.y); a0.z = fmaf(p0, wv.z, a0.z); a0.w = fmaf(p0, wv.w, a0.w);
        a1.x = fmaf(p1, wv.x, a1.x); a1.y = fmaf(p1, wv.y, a1.y); a1.z = fmaf(p1, wv.z, a1.z); a1.w = fmaf(p1, wv.w, a1.w);
        a2.x = fmaf(p2, wv.x, a2.x); a2.y = fmaf(p2, wv.y, a2.y); a2.z = fmaf(p2, wv.z, a2.z); a2.w = fmaf(p2, wv.w, a2.w);
        a3.x = fmaf(p3, wv.x, a3.x); a3.y = fmaf(p3, wv.y, a3.y); a3.z = fmaf(p3, wv.z, a3.z); a3.w = fmaf(p3, wv.w, a3.w);
    }
    #define STH4(dst, v) do { \
        *(__half2*)&(dst)[0] = __floats2half2_rn(v.x, v.y); \
        *(__half2*)&(dst)[2] = __floats2half2_rn(v.z, v.w); } while (0)
    STH4(&g_Whg[0L * K2 * DD + pidx], a0);
    STH4(&g_Whg[1L * K2 * DD + pidx], a1);
    STH4(&g_Whg[2L * K2 * DD + pidx], a2);
    STH4(&g_Whg[3L * K2 * DD + pidx], a3);
}

__global__ void mix_out_kernel(const float* __restrict__ w) {
    __shared__ float p[BB * EE];
    if (threadIdx.x < BB * EE) p[threadIdx.x] = g_probs[threadIdx.x];
    __syncthreads();
    long idx = ((long)blockIdx.x * blockDim.x + threadIdx.x) * 4;
    if (idx >= (long)DD * DD) return;
    float4 a0 = {0,0,0,0}, a1 = {0,0,0,0}, a2 = {0,0,0,0}, a3 = {0,0,0,0};
    #pragma unroll
    for (int e = 0; e < EE; e++) {
        float4 wv = *(const float4*)&w[(long)e * DD * DD + idx];
        float p0 = p[0*EE+e], p1 = p[1*EE+e], p2 = p[2*EE+e], p3 = p[3*EE+e];
        a0.x = fmaf(p0, wv.x, a0.x); a0.y = fmaf(p0, wv.y, a0.y); a0.z = fmaf(p0, wv.z, a0.z); a0.w = fmaf(p0, wv.w, a0.w);
        a1.x = fmaf(p1, wv.x, a1.x); a1.y = fmaf(p1, wv.y, a1.y); a1.z = fmaf(p1, wv.z, a1.z); a1.w = fmaf(p1, wv.w, a1.w);
        a2.x = fmaf(p2, wv.x, a2.x); a2.y = fmaf(p2, wv.y, a2.y); a2.z = fmaf(p2, wv.z, a2.z); a2.w = fmaf(p2, wv.w, a2.w);
        a3.x = fmaf(p3, wv.x, a3.x); a3.y = fmaf(p3, wv.y, a3.y); a3.z = fmaf(p3, wv.z, a3.z); a3.w = fmaf(p3, wv.w, a3.w);
    }
    STH4(&g_Wout[0L * DD * DD + idx], a0);
    STH4(&g_Wout[1L * DD * DD + idx], a1);
    STH4(&g_Wout[2L * DD * DD + idx], a2);
    STH4(&g_Wout[3L * DD * DD + idx], a3);
}

// ---------------- fp16 mma.sync NT GEMM, templated ----------------
// BNT: CTA N-tile. NTN: per-warp n-subtiles (warp tile 64 x 8*NTN).
// CV=true: N-cols are interleaved (hidden_j, gate_j); epilogue computes c,v
// and stores to g_c/g_v. CV=false: standard C = A@B^T + Add.
template <int BNT, int NTN, bool CV>
__global__ __launch_bounds__(256, 1)
void gemm_fp16_kernel(const __half* __restrict__ Aall, const __half* __restrict__ Ball,
                      float* __restrict__ Call, const float* __restrict__ AddAll,
                      int N, long strideB) {
    constexpr int B_STAGE_HALVES = BNT * SPADH;
    constexpr int STAGE_HALVES = A_STAGE_HALVES + B_STAGE_HALVES;
    constexpr int STAGE_BYTES = STAGE_HALVES * 2;
    extern __shared__ __align__(16) __half smh[];
    const uint32_t sb = smem_u32(smh);
    const int K = DD;
    const int bz = blockIdx.z;
    const __half* A  = Aall + (long)bz * SS * K;
    const __half* Bm = Ball + (long)bz * strideB;
    float* C = Call ? (Call + (long)bz * SS * N) : nullptr;
    const float* Add = AddAll ? (AddAll + (long)bz * SS * N) : nullptr;

    const int tid = threadIdx.x;
    const int lane = tid & 31;
    const int w = tid >> 5;
    const int wm = w & 1;
    const int wn = w >> 1;
    const int g = lane >> 2;
    const int tg = lane & 3;

    const int row0 = blockIdx.y * BM;
    const int col0 = blockIdx.x * BNT;

    float acc[4][NTN][4];
    #pragma unroll
    for (int i = 0; i < 4; i++)
        #pragma unroll
        for (int j = 0; j < NTN; j++)
            #pragma unroll
            for (int r = 0; r < 4; r++) acc[i][j][r] = 0.f;

    auto fill = [&](int stage, int kc) {
        uint32_t abase = sb + stage * STAGE_BYTES;
        uint32_t bbase = abase + A_STAGE_HALVES * 2;
        const __half* Ak = A + kc * BK;
        #pragma unroll
        for (int i = 0; i < 4; i++) {
            int q = tid + i * 256, r = q >> 3, cg = q & 7;
            cpasync16(abase + r * (SPADH * 2) + cg * 16, Ak + (long)(row0 + r) * K + cg * 8);
        }
        const __half* Bk = Bm + kc * BK;
        #pragma unroll
        for (int i = 0; i < BNT / 32; i++) {
            int q = tid + i * 256, r = q >> 3, cg = q & 7;
            cpasync16(bbase + r * (SPADH * 2) + cg * 16, Bk + (long)(col0 + r) * K + cg * 8);
        }
        asm volatile("cp.async.commit_group;" ::: "memory");
    };

    fill(0, 0);
    fill(1, 1);

    for (int kt = 0; kt < NKC; kt++) {
        if (kt + 2 < NKC) asm volatile("cp.async.wait_group 1;" ::: "memory");
        else              asm volatile("cp.async.wait_group 0;" ::: "memory");
        __syncthreads();

        if (kt + 2 < NKC) fill((kt + 2) % NSTAGE, kt + 2);

        const __half* sA = smh + (kt % NSTAGE) * STAGE_HALVES;
        const __half* sB = sA + A_STAGE_HALVES;

        #pragma unroll
        for (int ks = 0; ks < BK; ks += 16) {
            unsigned af[4][4], bf[NTN][2];
            #pragma unroll
            for (int mt = 0; mt < 4; mt++) {
                int r = wm * 64 + mt * 16 + g;
                af[mt][0] = *(const unsigned*)&sA[r * SPADH + ks + 2 * tg];
                af[mt][1] = *(const unsigned*)&sA[(r + 8) * SPADH + ks + 2 * tg];
                af[mt][2] = *(const unsigned*)&sA[r * SPADH + ks + 2 * tg + 8];
                af[mt][3] = *(const unsigned*)&sA[(r + 8) * SPADH + ks + 2 * tg + 8];
            }
            #pragma unroll
            for (int nt = 0; nt < NTN; nt++) {
                int c = wn * (NTN * 8) + nt * 8 + g;
                bf[nt][0] = *(const unsigned*)&sB[c * SPADH + ks + 2 * tg];
                bf[nt][1] = *(const unsigned*)&sB[c * SPADH + ks + 2 * tg + 8];
            }
            #pragma unroll
            for (int mt = 0; mt < 4; mt++)
                #pragma unroll
                for (int nt = 0; nt < NTN; nt++) {
                    asm volatile(
                        "mma.sync.aligned.m16n8k16.row.col.f32.f16.f16.f32 "
                        "{%0,%1,%2,%3}, {%4,%5,%6,%7}, {%8,%9}, {%0,%1,%2,%3};\n"
                        : "+f"(acc[mt][nt][0]), "+f"(acc[mt][nt][1]),
                          "+f"(acc[mt][nt][2]), "+f"(acc[mt][nt][3])
                        : "r"(af[mt][0]), "r"(af[mt][1]), "r"(af[mt][2]), "r"(af[mt][3]),
                          "r"(bf[nt][0]), "r"(bf[nt][1]));
                }
        }
        __syncthreads();
    }

    // epilogue
    #pragma unroll
    for (int mt = 0; mt < 4; mt++) {
        int row = row0 + wm * 64 + mt * 16 + g;
        #pragma unroll
        for (int nt = 0; nt < NTN; nt++) {
            int col = col0 + wn * (NTN * 8) + nt * 8 + 2 * tg;
            if (CV) {
                // cols (col, col+1) = (hidden_j, gate_j), j = col/2
                int j = col >> 1;
                long base0 = ((long)bz * SS + row) * DD + j;
                long base1 = ((long)bz * SS + row + 8) * DD + j;
                float c0, v0, c1, v1;
                cv_from_hg(acc[mt][nt][0], acc[mt][nt][1], c0, v0);
                cv_from_hg(acc[mt][nt][2], acc[mt][nt][3], c1, v1);
                g_c[base0] = c0; g_v[base0] = v0;
                g_c[base1] = c1; g_v[base1] = v1;
            } else {
                float2 v0 = make_float2(acc[mt][nt][0], acc[mt][nt][1]);
                float2 v1 = make_float2(acc[mt][nt][2], acc[mt][nt][3]);
                if (Add) {
                    float2 a0 = *(const float2*)&Add[(long)row * N + col];
                    float2 a1 = *(const float2*)&Add[(long)(row + 8) * N + col];
                    v0.x += a0.x; v0.y += a0.y; v1.x += a1.x; v1.y += a1.y;
                }
                *(float2*)&C[(long)row * N + col] = v0;
                *(float2*)&C[(long)(row + 8) * N + col] = v1;
            }
        }
    }
}

// ---------------- chunked scan (pure memory now) ----------------
__global__ void scanA_kernel() {
    int t = blockIdx.x * blockDim.x + threadIdx.x;
    if (t >= BB * NCHUNK * DD) return;
    int j = t % DD, ch = (t / DD) % NCHUNK, b = t / (DD * NCHUNK);
    long base = ((long)b * SS + (long)ch * CHUNK) * DD + j;
    float h = 0.f, Cp = 1.f;
    #pragma unroll 4
    for (int i = 0; i < CHUNK; i++) {
        float c = g_c[base + (long)i * DD];
        float v = g_v[base + (long)i * DD];
        h = fmaf(c, h, v);
        Cp *= c;
    }
    g_chunkC[t] = Cp;
    g_chunkH[t] = h;
}

__global__ void scanB_kernel() {
    int t = blockIdx.x * blockDim.x + threadIdx.x;
    if (t >= BB * DD) return;
    int b = t / DD, j = t % DD;
    float hin = 0.f;
    for (int ch = 0; ch < NCHUNK; ch++) {
        int u = (b * NCHUNK + ch) * DD + j;
        g_hin[u] = hin;
        hin = fmaf(g_chunkC[u], hin, g_chunkH[u]);
    }
}

__global__ void scanC_kernel(float* __restrict__ out) {
    int t = blockIdx.x * blockDim.x + threadIdx.x;
    if (t >= BB * NCHUNK * DD) return;
    int j = t % DD, ch = (t / DD) % NCHUNK, b = t / (DD * NCHUNK);
    long base = ((long)b * SS + (long)ch * CHUNK) * DD + j;
    float h = g_hin[t];
    #pragma unroll 4
    for (int i = 0; i < CHUNK; i++) {
        float c = g_c[base + (long)i * DD];
        float v = g_v[base + (long)i * DD];
        h = fmaf(c, h, v);
        g_h[base + (long)i * DD] = __float2half_rn(h);
    }
    if (ch == NCHUNK - 1) out[(long)BB * SS * DD + b * DD + j] = h;  // new_state
    if (t == 0) out[(long)BB * SS * DD + BB * DD] = 0.f;             // aux_loss
}

// ---------------- launch ----------------
extern "C" void kernel_launch(void* const* d_in, const int* in_sizes, int n_in,
                              void* d_out, int out_size) {
    const float* inputs   = (const float*)d_in[0];
    const float* norm_w   = (const float*)d_in[1];
    const float* router_w = (const float*)d_in[2];
    const float* router_b = (const float*)d_in[3];
    const float* w_hg     = (const float*)d_in[4];
    const float* w_out    = (const float*)d_in[5];
    float* out = (float*)d_out;

    __half* x_p;    cudaGetSymbolAddress((void**)&x_p, g_x);
    __half* Whg_p;  cudaGetSymbolAddress((void**)&Whg_p, g_Whg);
    __half* Wout_p; cudaGetSymbolAddress((void**)&Wout_p, g_Wout);
    __half* h_p;    cudaGetSymbolAddress((void**)&h_p, g_h);

    constexpr int SMEM1 = NSTAGE * (A_STAGE_HALVES + 256 * SPADH) * 2;  // 165888
    constexpr int SMEM2 = NSTAGE * (A_STAGE_HALVES + 128 * SPADH) * 2;  // 110592
    cudaFuncSetAttribute((const void*)gemm_fp16_kernel<256, 8, true>,
                         cudaFuncAttributeMaxDynamicSharedMemorySize, SMEM1);
    cudaFuncSetAttribute((const void*)gemm_fp16_kernel<128, 4, false>,
                         cudaFuncAttributeMaxDynamicSharedMemorySize, SMEM2);

    rmsnorm_kernel<<<BB * SS, 256>>>(inputs, norm_w);
    colmean_kernel<<<(BB * DD + 255) / 256, 256>>>();
    router_kernel<<<1, 256>>>(router_w, router_b);
    mix_hg_kernel<<<(K2 * DD / 4) / 256, 256>>>(w_hg);
    mix_out_kernel<<<(DD * DD / 4) / 256, 256>>>(w_out);

    // GEMM1: hg = x @ Whg^T with interleaved cols; epilogue emits c,v
    gemm_fp16_kernel<256, 8, true><<<dim3(K2 / 256, SS / BM, BB), 256, SMEM1>>>(
        x_p, Whg_p, nullptr, nullptr, K2, (long)K2 * DD);

    scanA_kernel<<<(BB * NCHUNK * DD + 255) / 256, 256>>>();
    scanB_kernel<<<(BB * DD + 255) / 256, 256>>>();
    scanC_kernel<<<(BB * NCHUNK * DD + 255) / 256, 256>>>(out);

    // GEMM2: out = h @ Wout^T + inputs
    gemm_fp16_kernel<128, 4, false><<<dim3(DD / 128, SS / BM, BB), 256, SMEM2>>>(
        h_p, Wout_p, out, inputs, DD, (long)DD * DD);
}

// round 13
// speedup vs baseline: 3.7149x; 1.0924x over previous
#include <cuda_runtime.h>
#include <cuda_fp16.h>
#include <math.h>
#include <stdint.h>

#define BB 4
#define SS 2048
#define DD 1024
#define EE 8
#define K2 2048
#define EPSV 1e-6f
#define NCHUNK 16
#define CHUNK (SS / NCHUNK)   // 128

// ---------------- GEMM tiling (fp16 operands) ----------------
#define BM 128
#define BK 64                     // halves per K-chunk (128 bytes/row)
#define NKC (DD / BK)             // 16
#define SPADH 72                  // smem row stride in halves (64 + 8)
#define A_STAGE_HALVES (BM * SPADH)              // 9216
#define NSTAGE 3

// ---------------- scratch ----------------
__device__ __half g_x[BB * SS * DD];
__device__ float  g_xmean[BB * DD];
__device__ float  g_probs[BB * EE];
__device__ __half g_Whg[BB * K2 * DD];    // row-permuted: 2j=hidden_j, 2j+1=gate_j
__device__ __half g_Wout[BB * DD * DD];
__device__ float  g_c[BB * SS * DD];
__device__ float  g_v[BB * SS * DD];
__device__ __half g_h[BB * SS * DD];
__device__ float  g_chunkC[BB * NCHUNK * DD];
__device__ float  g_chunkH[BB * NCHUNK * DD];
__device__ float  g_hin[BB * NCHUNK * DD];

// ---------------- helpers ----------------
__device__ __forceinline__ uint32_t smem_u32(const void* p) {
    uint32_t a;
    asm("{ .reg .u64 t; cvta.to.shared.u64 t, %1; cvt.u32.u64 %0, t; }" : "=r"(a) : "l"(p));
    return a;
}
__device__ __forceinline__ void cpasync16(uint32_t dst, const void* src) {
    asm volatile("cp.async.cg.shared.global [%0], [%1], 16;" :: "r"(dst), "l"(src));
}
// c = sigmoid(-gate); v = sigmoid(gate) * (hidden>=0 ? hidden+0.5 : sigmoid(hidden))
__device__ __forceinline__ void cv_from_hg(float hidden, float gate, float& c, float& v) {
    float t = expf(-fabsf(gate));
    float inv = 1.0f / (1.0f + t);
    float sp;
    if (gate >= 0.f) { sp = inv; c = t * inv; }
    else             { sp = t * inv; c = inv; }
    float gh = (hidden >= 0.f) ? (hidden + 0.5f) : (1.0f / (1.0f + expf(-hidden)));
    v = sp * gh;
}

// ---------------- 1. RMSNorm (writes fp16 x) ----------------
__global__ void rmsnorm_kernel(const float* __restrict__ inp, const float* __restrict__ nw) {
    int row = blockIdx.x;
    const float* in = inp + (long)row * DD;
    __half* out = g_x + (long)row * DD;
    float ss = 0.f;
    for (int d = threadIdx.x; d < DD; d += 256) { float t = in[d]; ss += t * t; }
    __shared__ float red[256];
    red[threadIdx.x] = ss; __syncthreads();
    for (int s = 128; s > 0; s >>= 1) {
        if (threadIdx.x < s) red[threadIdx.x] += red[threadIdx.x + s];
        __syncthreads();
    }
    float scale = rsqrtf(red[0] * (1.0f / DD) + EPSV);
    for (int d = threadIdx.x; d < DD; d += 256) out[d] = __float2half_rn(in[d] * scale * nw[d]);
}

// ---------------- 2. column mean ----------------
__global__ void colmean_kernel() {
    int t = blockIdx.x * blockDim.x + threadIdx.x;
    if (t >= BB * DD) return;
    int b = t / DD, d = t % DD;
    float s = 0.f;
    const __half* base = g_x + (long)b * SS * DD + d;
    for (int i = 0; i < SS; i++) s += __half2float(base[(long)i * DD]);
    g_xmean[t] = s * (1.0f / SS);
}

// ---------------- 3. router ----------------
__global__ void router_kernel(const float* __restrict__ rw, const float* __restrict__ rb) {
    __shared__ float logits[BB * EE];
    int tid = threadIdx.x, warp = tid / 32, lane = tid % 32;
    for (int p = warp; p < BB * EE; p += 8) {
        int b = p / EE, e = p % EE;
        float s = 0.f;
        for (int d = lane; d < DD; d += 32) s += g_xmean[b * DD + d] * rw[e * DD + d];
        for (int o = 16; o > 0; o >>= 1) s += __shfl_xor_sync(0xffffffffu, s, o);
        if (lane == 0) logits[p] = s + rb[e];
    }
    __syncthreads();
    if (tid < BB) {
        float mx = -1e30f;
        for (int e = 0; e < EE; e++) mx = fmaxf(mx, logits[tid * EE + e]);
        float ex[EE]; float sum = 0.f;
        for (int e = 0; e < EE; e++) { ex[e] = expf(logits[tid * EE + e] - mx); sum += ex[e]; }
        float inv = 1.0f / sum;
        for (int e = 0; e < EE; e++) g_probs[tid * EE + e] = ex[e] * inv;
    }
}

// ---------------- 4. mix expert weights (fp32 accum, fp16 out) ----------------
// hg weights written ROW-PERMUTED: output row 2j <- hidden_j (k=j),
// row 2j+1 <- gate_j (k=j+DD). GEMM1 then produces interleaved hidden/gate cols.
__global__ void mix_hg_kernel(const float* __restrict__ w) {
    __shared__ float p[BB * EE];
    if (threadIdx.x < BB * EE) p[threadIdx.x] = g_probs[threadIdx.x];
    __syncthreads();
    long idx = ((long)blockIdx.x * blockDim.x + threadIdx.x) * 4;
    if (idx >= (long)K2 * DD) return;
    int k = (int)(idx / DD), d = (int)(idx % DD);
    int pr = (k < DD) ? 2 * k : 2 * (k - DD) + 1;
    long pidx = (long)pr * DD + d;
    float4 a0 = {0,0,0,0}, a1 = {0,0,0,0}, a2 = {0,0,0,0}, a3 = {0,0,0,0};
    #pragma unroll
    for (int e = 0; e < EE; e++) {
        float4 wv = *(const float4*)&w[(long)e * K2 * DD + idx];
        float p0 = p[0*EE+e], p1 = p[1*EE+e], p2 = p[2*EE+e], p3 = p[3*EE+e];
        a0.x = fmaf(p0, wv.x, a0.x); a0.y = fmaf(p0, wv.y, a0.y); a0.z = fmaf(p0, wv.z, a0.z); a0.w = fmaf(p0, wv.w, a0.w);
        a1.x = fmaf(p1, wv.x, a1.x); a1.y = fmaf(p1, wv.y, a1.y); a1.z = fmaf(p1, wv.z, a1.z); a1.w = fmaf(p1, wv.w, a1.w);
        a2.x = fmaf(p2, wv.x, a2.x); a2.y = fmaf(p2, wv.y, a2.y); a2.z = fmaf(p2, wv.z, a2.z); a2.w = fmaf(p2, wv.w, a2.w);
        a3.x = fmaf(p3, wv.x, a3.x); a3.y = fmaf(p3, wv.y, a3.y); a3.z = fmaf(p3, wv.z, a3.z); a3.w = fmaf(p3, wv.w, a3.w);
    }
    #define STH4(dst, v) do { \
        *(__half2*)&(dst)[0] = __floats2half2_rn(v.x, v.y); \
        *(__half2*)&(dst)[2] = __floats2half2_rn(v.z, v.w); } while (0)
    STH4(&g_Whg[0L * K2 * DD + pidx], a0);
    STH4(&g_Whg[1L * K2 * DD + pidx], a1);
    STH4(&g_Whg[2L * K2 * DD + pidx], a2);
    STH4(&g_Whg[3L * K2 * DD + pidx], a3);
}

__global__ void mix_out_kernel(const float* __restrict__ w) {
    __shared__ float p[BB * EE];
    if (threadIdx.x < BB * EE) p[threadIdx.x] = g_probs[threadIdx.x];
    __syncthreads();
    long idx = ((long)blockIdx.x * blockDim.x + threadIdx.x) * 4;
    if (idx >= (long)DD * DD) return;
    float4 a0 = {0,0,0,0}, a1 = {0,0,0,0}, a2 = {0,0,0,0}, a3 = {0,0,0,0};
    #pragma unroll
    for (int e = 0; e < EE; e++) {
        float4 wv = *(const float4*)&w[(long)e * DD * DD + idx];
        float p0 = p[0*EE+e], p1 = p[1*EE+e], p2 = p[2*EE+e], p3 = p[3*EE+e];
        a0.x = fmaf(p0, wv.x, a0.x); a0.y = fmaf(p0, wv.y, a0.y); a0.z = fmaf(p0, wv.z, a0.z); a0.w = fmaf(p0, wv.w, a0.w);
        a1.x = fmaf(p1, wv.x, a1.x); a1.y = fmaf(p1, wv.y, a1.y); a1.z = fmaf(p1, wv.z, a1.z); a1.w = fmaf(p1, wv.w, a1.w);
        a2.x = fmaf(p2, wv.x, a2.x); a2.y = fmaf(p2, wv.y, a2.y); a2.z = fmaf(p2, wv.z, a2.z); a2.w = fmaf(p2, wv.w, a2.w);
        a3.x = fmaf(p3, wv.x, a3.x); a3.y = fmaf(p3, wv.y, a3.y); a3.z = fmaf(p3, wv.z, a3.z); a3.w = fmaf(p3, wv.w, a3.w);
    }
    STH4(&g_Wout[0L * DD * DD + idx], a0);
    STH4(&g_Wout[1L * DD * DD + idx], a1);
    STH4(&g_Wout[2L * DD * DD + idx], a2);
    STH4(&g_Wout[3L * DD * DD + idx], a3);
}

// ---------------- fp16 mma.sync NT GEMM, templated ----------------
// BNT=128 CTA N-tile, 2 CTAs/SM (16 warps/SM). Warp tile 64 x 8*NTN.
// CV=true: N-cols interleaved (hidden_j, gate_j); epilogue computes c,v.
template <int BNT, int NTN, bool CV>
__global__ __launch_bounds__(256, 2)
void gemm_fp16_kernel(const __half* __restrict__ Aall, const __half* __restrict__ Ball,
                      float* __restrict__ Call, const float* __restrict__ AddAll,
                      int N, long strideB) {
    constexpr int B_STAGE_HALVES = BNT * SPADH;
    constexpr int STAGE_HALVES = A_STAGE_HALVES + B_STAGE_HALVES;
    constexpr int STAGE_BYTES = STAGE_HALVES * 2;
    extern __shared__ __align__(16) __half smh[];
    const uint32_t sb = smem_u32(smh);
    const int K = DD;
    const int bz = blockIdx.z;
    const __half* A  = Aall + (long)bz * SS * K;
    const __half* Bm = Ball + (long)bz * strideB;
    float* C = Call ? (Call + (long)bz * SS * N) : nullptr;
    const float* Add = AddAll ? (AddAll + (long)bz * SS * N) : nullptr;

    const int tid = threadIdx.x;
    const int lane = tid & 31;
    const int w = tid >> 5;
    const int wm = w & 1;
    const int wn = w >> 1;
    const int g = lane >> 2;
    const int tg = lane & 3;

    const int row0 = blockIdx.y * BM;
    const int col0 = blockIdx.x * BNT;

    float acc[4][NTN][4];
    #pragma unroll
    for (int i = 0; i < 4; i++)
        #pragma unroll
        for (int j = 0; j < NTN; j++)
            #pragma unroll
            for (int r = 0; r < 4; r++) acc[i][j][r] = 0.f;

    auto fill = [&](int stage, int kc) {
        uint32_t abase = sb + stage * STAGE_BYTES;
        uint32_t bbase = abase + A_STAGE_HALVES * 2;
        const __half* Ak = A + kc * BK;
        #pragma unroll
        for (int i = 0; i < 4; i++) {
            int q = tid + i * 256, r = q >> 3, cg = q & 7;
            cpasync16(abase + r * (SPADH * 2) + cg * 16, Ak + (long)(row0 + r) * K + cg * 8);
        }
        const __half* Bk = Bm + kc * BK;
        #pragma unroll
        for (int i = 0; i < BNT / 32; i++) {
            int q = tid + i * 256, r = q >> 3, cg = q & 7;
            cpasync16(bbase + r * (SPADH * 2) + cg * 16, Bk + (long)(col0 + r) * K + cg * 8);
        }
        asm volatile("cp.async.commit_group;" ::: "memory");
    };

    fill(0, 0);
    fill(1, 1);

    for (int kt = 0; kt < NKC; kt++) {
        if (kt + 2 < NKC) asm volatile("cp.async.wait_group 1;" ::: "memory");
        else              asm volatile("cp.async.wait_group 0;" ::: "memory");
        __syncthreads();

        if (kt + 2 < NKC) fill((kt + 2) % NSTAGE, kt + 2);

        const __half* sA = smh + (kt % NSTAGE) * STAGE_HALVES;
        const __half* sB = sA + A_STAGE_HALVES;

        #pragma unroll
        for (int ks = 0; ks < BK; ks += 16) {
            unsigned af[4][4], bf[NTN][2];
            #pragma unroll
            for (int mt = 0; mt < 4; mt++) {
                int r = wm * 64 + mt * 16 + g;
                af[mt][0] = *(const unsigned*)&sA[r * SPADH + ks + 2 * tg];
                af[mt][1] = *(const unsigned*)&sA[(r + 8) * SPADH + ks + 2 * tg];
                af[mt][2] = *(const unsigned*)&sA[r * SPADH + ks + 2 * tg + 8];
                af[mt][3] = *(const unsigned*)&sA[(r + 8) * SPADH + ks + 2 * tg + 8];
            }
            #pragma unroll
            for (int nt = 0; nt < NTN; nt++) {
                int c = wn * (NTN * 8) + nt * 8 + g;
                bf[nt][0] = *(const unsigned*)&sB[c * SPADH + ks + 2 * tg];
                bf[nt][1] = *(const unsigned*)&sB[c * SPADH + ks + 2 * tg + 8];
            }
            #pragma unroll
            for (int mt = 0; mt < 4; mt++)
                #pragma unroll
                for (int nt = 0; nt < NTN; nt++) {
                    asm volatile(
                        "mma.sync.aligned.m16n8k16.row.col.f32.f16.f16.f32 "
                        "{%0,%1,%2,%3}, {%4,%5,%6,%7}, {%8,%9}, {%0,%1,%2,%3};\n"
                        : "+f"(acc[mt][nt][0]), "+f"(acc[mt][nt][1]),
                          "+f"(acc[mt][nt][2]), "+f"(acc[mt][nt][3])
                        : "r"(af[mt][0]), "r"(af[mt][1]), "r"(af[mt][2]), "r"(af[mt][3]),
                          "r"(bf[nt][0]), "r"(bf[nt][1]));
                }
        }
        __syncthreads();
    }

    // epilogue
    #pragma unroll
    for (int mt = 0; mt < 4; mt++) {
        int row = row0 + wm * 64 + mt * 16 + g;
        #pragma unroll
        for (int nt = 0; nt < NTN; nt++) {
            int col = col0 + wn * (NTN * 8) + nt * 8 + 2 * tg;
            if (CV) {
                // cols (col, col+1) = (hidden_j, gate_j), j = col/2
                int j = col >> 1;
                long base0 = ((long)bz * SS + row) * DD + j;
                long base1 = ((long)bz * SS + row + 8) * DD + j;
                float c0, v0, c1, v1;
                cv_from_hg(acc[mt][nt][0], acc[mt][nt][1], c0, v0);
                cv_from_hg(acc[mt][nt][2], acc[mt][nt][3], c1, v1);
                g_c[base0] = c0; g_v[base0] = v0;
                g_c[base1] = c1; g_v[base1] = v1;
            } else {
                float2 v0 = make_float2(acc[mt][nt][0], acc[mt][nt][1]);
                float2 v1 = make_float2(acc[mt][nt][2], acc[mt][nt][3]);
                if (Add) {
                    float2 a0 = *(const float2*)&Add[(long)row * N + col];
                    float2 a1 = *(const float2*)&Add[(long)(row + 8) * N + col];
                    v0.x += a0.x; v0.y += a0.y; v1.x += a1.x; v1.y += a1.y;
                }
                *(float2*)&C[(long)row * N + col] = v0;
                *(float2*)&C[(long)(row + 8) * N + col] = v1;
            }
        }
    }
}

// ---------------- chunked scan (pure memory) ----------------
__global__ void scanA_kernel() {
    int t = blockIdx.x * blockDim.x + threadIdx.x;
    if (t >= BB * NCHUNK * DD) return;
    int j = t % DD, ch = (t / DD) % NCHUNK, b = t / (DD * NCHUNK);
    long base = ((long)b * SS + (long)ch * CHUNK) * DD + j;
    float h = 0.f, Cp = 1.f;
    #pragma unroll 4
    for (int i = 0; i < CHUNK; i++) {
        float c = g_c[base + (long)i * DD];
        float v = g_v[base + (long)i * DD];
        h = fmaf(c, h, v);
        Cp *= c;
    }
    g_chunkC[t] = Cp;
    g_chunkH[t] = h;
}

__global__ void scanB_kernel() {
    int t = blockIdx.x * blockDim.x + threadIdx.x;
    if (t >= BB * DD) return;
    int b = t / DD, j = t % DD;
    float hin = 0.f;
    for (int ch = 0; ch < NCHUNK; ch++) {
        int u = (b * NCHUNK + ch) * DD + j;
        g_hin[u] = hin;
        hin = fmaf(g_chunkC[u], hin, g_chunkH[u]);
    }
}

__global__ void scanC_kernel(float* __restrict__ out) {
    int t = blockIdx.x * blockDim.x + threadIdx.x;
    if (t >= BB * NCHUNK * DD) return;
    int j = t % DD, ch = (t / DD) % NCHUNK, b = t / (DD * NCHUNK);
    long base = ((long)b * SS + (long)ch * CHUNK) * DD + j;
    float h = g_hin[t];
    #pragma unroll 4
    for (int i = 0; i < CHUNK; i++) {
        float c = g_c[base + (long)i * DD];
        float v = g_v[base + (long)i * DD];
        h = fmaf(c, h, v);
        g_h[base + (long)i * DD] = __float2half_rn(h);
    }
    if (ch == NCHUNK - 1) out[(long)BB * SS * DD + b * DD + j] = h;  // new_state
    if (t == 0) out[(long)BB * SS * DD + BB * DD] = 0.f;             // aux_loss
}

// ---------------- launch ----------------
extern "C" void kernel_launch(void* const* d_in, const int* in_sizes, int n_in,
                              void* d_out, int out_size) {
    const float* inputs   = (const float*)d_in[0];
    const float* norm_w   = (const float*)d_in[1];
    const float* router_w = (const float*)d_in[2];
    const float* router_b = (const float*)d_in[3];
    const float* w_hg     = (const float*)d_in[4];
    const float* w_out    = (const float*)d_in[5];
    float* out = (float*)d_out;

    __half* x_p;    cudaGetSymbolAddress((void**)&x_p, g_x);
    __half* Whg_p;  cudaGetSymbolAddress((void**)&Whg_p, g_Whg);
    __half* Wout_p; cudaGetSymbolAddress((void**)&Wout_p, g_Wout);
    __half* h_p;    cudaGetSymbolAddress((void**)&h_p, g_h);

    constexpr int SMEMB = NSTAGE * (A_STAGE_HALVES + 128 * SPADH) * 2;  // 110592
    cudaFuncSetAttribute((const void*)gemm_fp16_kernel<128, 4, true>,
                         cudaFuncAttributeMaxDynamicSharedMemorySize, SMEMB);
    cudaFuncSetAttribute((const void*)gemm_fp16_kernel<128, 4, false>,
                         cudaFuncAttributeMaxDynamicSharedMemorySize, SMEMB);

    rmsnorm_kernel<<<BB * SS, 256>>>(inputs, norm_w);
    colmean_kernel<<<(BB * DD + 255) / 256, 256>>>();
    router_kernel<<<1, 256>>>(router_w, router_b);
    mix_hg_kernel<<<(K2 * DD / 4) / 256, 256>>>(w_hg);
    mix_out_kernel<<<(DD * DD / 4) / 256, 256>>>(w_out);

    // GEMM1: hg = x @ Whg^T with interleaved cols; epilogue emits c,v
    gemm_fp16_kernel<128, 4, true><<<dim3(K2 / 128, SS / BM, BB), 256, SMEMB>>>(
        x_p, Whg_p, nullptr, nullptr, K2, (long)K2 * DD);

    scanA_kernel<<<(BB * NCHUNK * DD + 255) / 256, 256>>>();
    scanB_kernel<<<(BB * DD + 255) / 256, 256>>>();
    scanC_kernel<<<(BB * NCHUNK * DD + 255) / 256, 256>>>(out);

    // GEMM2: out = h @ Wout^T + inputs
    gemm_fp16_kernel<128, 4, false><<<dim3(DD / 128, SS / BM, BB), 256, SMEMB>>>(
        h_p, Wout_p, out, inputs, DD, (long)DD * DD);
}